// round 6
// baseline (speedup 1.0000x reference)
#include <cuda_runtime.h>
#include <cuda_bf16.h>
#include <math.h>
#include <stdint.h>

#define NN 51200      // nodes
#define NE 819200     // edges
#define HD 128        // hidden / in dim
#define NG 128        // graphs
#define SEG 400       // nodes per graph
#define OUTC 10
#define NT  (NN / 128)          // 400 M-tiles

// ---------------- scratch (device globals) ---------------------------------
__device__ float g_x[NN * HD];     // fp32 features (agg gather source)
__device__ float g_y[NN * HD];     // conv output (post-relu)
__device__ __align__(16) __nv_bfloat16 g_xh[NN * HD];   // bf16 hi of x
__device__ __align__(16) __nv_bfloat16 g_xl[NN * HD];   // bf16 lo of x
__device__ __align__(16) __nv_bfloat16 g_ah[NN * HD];   // bf16 hi of agg
__device__ __align__(16) __nv_bfloat16 g_al[NN * HD];   // bf16 lo of agg
// weight images, transposed [n][k] bf16, row-major: 4 matrices x (hi,lo)
__device__ __align__(16) __nv_bfloat16 g_w[8 * HD * HD];
__device__ int   g_src[NE];
__device__ int   g_dst[NE];
__device__ int   g_p1[NN];
__device__ int   g_p2[NN];
__device__ int   g_cnt[NN];
__device__ int   g_rowstart[NN + 1];
__device__ int   g_cursor[NN];
__device__ int   g_eidx[NE];
__device__ float g_pooled[NG * HD];
__device__ int   g_is64;

// ---------------- helpers ---------------------------------------------------
__device__ __forceinline__ uint32_t smem_to_u32(const void* p) {
    uint32_t a;
    asm("{ .reg .u64 t; cvta.to.shared.u64 t, %1; cvt.u32.u64 %0, t; }"
        : "=r"(a) : "l"(p));
    return a;
}
#define CP_ASYNC16(dst, src) \
    asm volatile("cp.async.cg.shared.global [%0], [%1], 16;" \
                 :: "r"(dst), "l"(src) : "memory")
#define CP_COMMIT() asm volatile("cp.async.commit_group;" ::: "memory")
#define CP_WAIT2()  asm volatile("cp.async.wait_group 2;" ::: "memory")

__device__ __forceinline__ void ldsm_x4(uint32_t* r, uint32_t addr) {
    asm volatile("ldmatrix.sync.aligned.m8n8.x4.shared.b16 {%0,%1,%2,%3}, [%4];"
                 : "=r"(r[0]), "=r"(r[1]), "=r"(r[2]), "=r"(r[3]) : "r"(addr));
}
__device__ __forceinline__ void mma16816(float* c, const uint32_t* a, const uint32_t* b) {
    asm volatile("mma.sync.aligned.m16n8k16.row.col.f32.bf16.bf16.f32 "
                 "{%0,%1,%2,%3},{%4,%5,%6,%7},{%8,%9},{%0,%1,%2,%3};"
                 : "+f"(c[0]), "+f"(c[1]), "+f"(c[2]), "+f"(c[3])
                 : "r"(a[0]), "r"(a[1]), "r"(a[2]), "r"(a[3]), "r"(b[0]), "r"(b[1]));
}

__device__ __forceinline__ void write_hilo(__nv_bfloat16* hi, __nv_bfloat16* lo,
                                           int node, int lane, float4 v) {
    int off = node * HD + lane * 4;
    __nv_bfloat16 hx = __float2bfloat16_rn(v.x), hy = __float2bfloat16_rn(v.y);
    __nv_bfloat16 hz = __float2bfloat16_rn(v.z), hw = __float2bfloat16_rn(v.w);
    uint2 ph, pl;
    ph.x = (uint32_t)__bfloat16_as_ushort(hx) | ((uint32_t)__bfloat16_as_ushort(hy) << 16);
    ph.y = (uint32_t)__bfloat16_as_ushort(hz) | ((uint32_t)__bfloat16_as_ushort(hw) << 16);
    __nv_bfloat16 gx = __float2bfloat16_rn(v.x - __bfloat162float(hx));
    __nv_bfloat16 gy = __float2bfloat16_rn(v.y - __bfloat162float(hy));
    __nv_bfloat16 gz = __float2bfloat16_rn(v.z - __bfloat162float(hz));
    __nv_bfloat16 gw = __float2bfloat16_rn(v.w - __bfloat162float(hw));
    pl.x = (uint32_t)__bfloat16_as_ushort(gx) | ((uint32_t)__bfloat16_as_ushort(gy) << 16);
    pl.y = (uint32_t)__bfloat16_as_ushort(gz) | ((uint32_t)__bfloat16_as_ushort(gw) << 16);
    *(uint2*)&hi[off] = ph;
    *(uint2*)&lo[off] = pl;
}

// ---------------- init: zero counters/pooled + dtype detect ----------------
__global__ void init_kernel(const unsigned* __restrict__ e) {
    int i = blockIdx.x * blockDim.x + threadIdx.x;
    if (i < NN) g_cnt[i] = 0;
    if (i < NG * HD) g_pooled[i] = 0.0f;
    if (i == 0) {
        int all0 = 1;
        #pragma unroll 1
        for (int k = 0; k < 128; k++)
            if (e[2 * k + 1] != 0u) { all0 = 0; break; }
        g_is64 = all0;
    }
}

// fused convert + histogram
__global__ void convhist_kernel(const void* __restrict__ eraw,
                                const void* __restrict__ p1raw,
                                const void* __restrict__ p2raw) {
    int i = blockIdx.x * blockDim.x + threadIdx.x;
    const bool is64 = (g_is64 != 0);
    if (i < NE) {
        int s = is64 ? (int)((const long long*)eraw)[i] : ((const int*)eraw)[i];
        int d = is64 ? (int)((const long long*)eraw)[NE + i] : ((const int*)eraw)[NE + i];
        g_src[i] = s;
        g_dst[i] = d;
        atomicAdd(&g_cnt[d], 1);
    }
    if (i < NN) {
        g_p1[i] = is64 ? (int)((const long long*)p1raw)[i] : ((const int*)p1raw)[i];
        g_p2[i] = is64 ? (int)((const long long*)p2raw)[i] : ((const int*)p2raw)[i];
    }
}

// ---------------- single-block fused scan (NN = 1024 * 50) -----------------
__global__ void __launch_bounds__(1024)
scan_kernel() {
    const int t = threadIdx.x;
    const int base = t * 50;
    int sum = 0;
    #pragma unroll 1
    for (int i = 0; i < 50; i++) sum += g_cnt[base + i];

    // block-wide exclusive scan of per-thread sums
    const int lane = t & 31, warp = t >> 5;
    int v = sum;
    #pragma unroll
    for (int off = 1; off < 32; off <<= 1) {
        int n = __shfl_up_sync(0xffffffffu, v, off);
        if (lane >= off) v += n;
    }
    __shared__ int ws[32];
    if (lane == 31) ws[warp] = v;
    __syncthreads();
    if (warp == 0) {
        int w = ws[lane];
        #pragma unroll
        for (int off = 1; off < 32; off <<= 1) {
            int n = __shfl_up_sync(0xffffffffu, w, off);
            if (lane >= off) w += n;
        }
        ws[lane] = w;
    }
    __syncthreads();
    int offset = (warp == 0) ? 0 : ws[warp - 1];
    int run = offset + v - sum;   // exclusive prefix for this thread's chunk

    #pragma unroll 1
    for (int i = 0; i < 50; i++) {
        g_rowstart[base + i] = run;
        g_cursor[base + i] = run;
        run += g_cnt[base + i];
    }
    if (t == 1023) g_rowstart[NN] = run;   // == NE
}

__global__ void scatter_kernel() {
    int e = blockIdx.x * blockDim.x + threadIdx.x;
    if (e < NE) {
        int pos = atomicAdd(&g_cursor[g_dst[e]], 1);
        g_eidx[pos] = g_src[e];
    }
}

// ---------------- one-time bf16 hi/lo conversion of x0 ---------------------
__global__ void conv0_kernel(const float* __restrict__ xin) {
    int warp = (blockIdx.x * blockDim.x + threadIdx.x) >> 5;
    if (warp >= NN) return;
    int lane = threadIdx.x & 31;
    float4 v = *(const float4*)&xin[(size_t)warp * HD + lane * 4];
    write_hilo(g_xh, g_xl, warp, lane, v);
}

// ---------------- weight prep: transpose + bf16 split ----------------------
__global__ void wprep_kernel(const float* __restrict__ W0r,
                             const float* __restrict__ W0e,
                             const float* __restrict__ W1r,
                             const float* __restrict__ W1e) {
    const float* Ws[4] = {W0r, W0e, W1r, W1e};
    const float* W = Ws[blockIdx.x];
    __nv_bfloat16* hi = g_w + (size_t)(2 * blockIdx.x) * HD * HD;
    __nv_bfloat16* lo = g_w + (size_t)(2 * blockIdx.x + 1) * HD * HD;
    int n = threadIdx.x;
    for (int k0 = 0; k0 < HD; k0 += 4) {
        float4 v;
        v.x = W[(k0 + 0) * HD + n];
        v.y = W[(k0 + 1) * HD + n];
        v.z = W[(k0 + 2) * HD + n];
        v.w = W[(k0 + 3) * HD + n];
        int off = n * HD + k0;
        __nv_bfloat16 hx = __float2bfloat16_rn(v.x), hy = __float2bfloat16_rn(v.y);
        __nv_bfloat16 hz = __float2bfloat16_rn(v.z), hw = __float2bfloat16_rn(v.w);
        uint2 ph, pl;
        ph.x = (uint32_t)__bfloat16_as_ushort(hx) | ((uint32_t)__bfloat16_as_ushort(hy) << 16);
        ph.y = (uint32_t)__bfloat16_as_ushort(hz) | ((uint32_t)__bfloat16_as_ushort(hw) << 16);
        __nv_bfloat16 gx = __float2bfloat16_rn(v.x - __bfloat162float(hx));
        __nv_bfloat16 gy = __float2bfloat16_rn(v.y - __bfloat162float(hy));
        __nv_bfloat16 gz = __float2bfloat16_rn(v.z - __bfloat162float(hz));
        __nv_bfloat16 gw = __float2bfloat16_rn(v.w - __bfloat162float(hw));
        pl.x = (uint32_t)__bfloat16_as_ushort(gx) | ((uint32_t)__bfloat16_as_ushort(gy) << 16);
        pl.y = (uint32_t)__bfloat16_as_ushort(gz) | ((uint32_t)__bfloat16_as_ushort(gw) << 16);
        *(uint2*)&hi[off] = ph;
        *(uint2*)&lo[off] = pl;
    }
}

// ---------------- aggregation: warp/node, unroll-4, emits bf16 hi/lo -------
__global__ void agg_kernel(const float* __restrict__ xin) {
    int warp = (blockIdx.x * blockDim.x + threadIdx.x) >> 5;
    if (warp >= NN) return;
    int lane = threadIdx.x & 31;
    int s = g_rowstart[warp];
    int e = g_rowstart[warp + 1];
    float4 acc = make_float4(0.f, 0.f, 0.f, 0.f);
    int j = s;
    for (; j + 3 < e; j += 4) {
        int u0 = g_eidx[j],     u1 = g_eidx[j + 1];
        int u2 = g_eidx[j + 2], u3 = g_eidx[j + 3];
        float4 v0 = *(const float4*)&xin[(size_t)u0 * HD + lane * 4];
        float4 v1 = *(const float4*)&xin[(size_t)u1 * HD + lane * 4];
        float4 v2 = *(const float4*)&xin[(size_t)u2 * HD + lane * 4];
        float4 v3 = *(const float4*)&xin[(size_t)u3 * HD + lane * 4];
        acc.x += (v0.x + v1.x) + (v2.x + v3.x);
        acc.y += (v0.y + v1.y) + (v2.y + v3.y);
        acc.z += (v0.z + v1.z) + (v2.z + v3.z);
        acc.w += (v0.w + v1.w) + (v2.w + v3.w);
    }
    for (; j < e; j++) {
        int u = g_eidx[j];
        float4 v = *(const float4*)&xin[(size_t)u * HD + lane * 4];
        acc.x += v.x; acc.y += v.y; acc.z += v.z; acc.w += v.w;
    }
    write_hilo(g_ah, g_al, warp, lane, acc);
}

// ---------------- HMMA GEMM: y = relu([x|agg] @ [Wroot;Wrel] + b) ----------
// 3-term bf16 split folded into one K=768 sweep. If pooled != nullptr, the
// epilogue segment-sums relu(out) into g_pooled instead of storing y.
__global__ void __launch_bounds__(256, 2)
gemm_kernel(const __nv_bfloat16* __restrict__ xh, const __nv_bfloat16* __restrict__ xl,
            const __nv_bfloat16* __restrict__ ah, const __nv_bfloat16* __restrict__ al,
            const __nv_bfloat16* __restrict__ wrh, const __nv_bfloat16* __restrict__ wrl,
            const __nv_bfloat16* __restrict__ weh, const __nv_bfloat16* __restrict__ wel,
            const float* __restrict__ bias, float* __restrict__ yout,
            float* __restrict__ pooled) {
    extern __shared__ char smem[];
    __shared__ const uint4* Atab[6];
    __shared__ const uint4* Btab[6];
    const int tid = threadIdx.x, lane = tid & 31, wid = tid >> 5;
    const int wm = wid >> 1, wn = wid & 1;
    const int tile = blockIdx.x;

    if (tid == 0) {
        size_t toff = (size_t)tile * 128 * HD;
        Atab[0] = (const uint4*)(xh + toff); Atab[1] = (const uint4*)(ah + toff);
        Atab[2] = (const uint4*)(xl + toff); Atab[3] = (const uint4*)(al + toff);
        Atab[4] = Atab[0];                   Atab[5] = Atab[1];
        Btab[0] = (const uint4*)wrh; Btab[1] = (const uint4*)weh;
        Btab[2] = (const uint4*)wrh; Btab[3] = (const uint4*)weh;
        Btab[4] = (const uint4*)wrl; Btab[5] = (const uint4*)wel;
    }
    __syncthreads();
    const uint32_t sbase = smem_to_u32(smem);

    auto prefetch = [&](int cc, int st) {
        int seg = cc >> 1, ko4 = (cc & 1) << 3;
        const uint4* As = Atab[seg];
        const uint4* Bs = Btab[seg];
        uint32_t sA = sbase + st * 32768;
        uint32_t sB = sA + 16384;
        #pragma unroll
        for (int i = 0; i < 4; i++) {
            int idx = tid + 256 * i;
            int row = idx >> 3, c4 = idx & 7;
            int sw = (row * 8 + (c4 ^ (row & 7))) * 16;
            CP_ASYNC16(sA + sw, As + row * 16 + ko4 + c4);
            CP_ASYNC16(sB + sw, Bs + row * 16 + ko4 + c4);
        }
    };

    prefetch(0, 0); CP_COMMIT();
    prefetch(1, 1); CP_COMMIT();
    prefetch(2, 2); CP_COMMIT();

    float acc[2][8][4] = {};
    int st = 0;
    #pragma unroll 1
    for (int c = 0; c < 12; c++) {
        CP_WAIT2();
        __syncthreads();
        uint32_t sA = sbase + st * 32768;
        uint32_t sB = sA + 16384;
        #pragma unroll
        for (int kk = 0; kk < 4; kk++) {
            uint32_t a0[4], a1[4];
            {
                int row = wm * 32 + (lane & 15);
                int c4 = kk * 2 + (lane >> 4);
                ldsm_x4(a0, sA + (row * 8 + (c4 ^ (row & 7))) * 16);
                int row1 = row + 16;
                ldsm_x4(a1, sA + (row1 * 8 + (c4 ^ (row1 & 7))) * 16);
            }
            uint32_t b[4][4];
            #pragma unroll
            for (int p = 0; p < 4; p++) {
                int nrow = wn * 64 + p * 16 + ((lane >> 4) << 3) + (lane & 7);
                int c4 = kk * 2 + ((lane >> 3) & 1);
                ldsm_x4(b[p], sB + (nrow * 8 + (c4 ^ (nrow & 7))) * 16);
            }
            #pragma unroll
            for (int nt = 0; nt < 8; nt++) {
                mma16816(acc[0][nt], a0, &b[nt >> 1][(nt & 1) * 2]);
                mma16816(acc[1][nt], a1, &b[nt >> 1][(nt & 1) * 2]);
            }
        }
        __syncthreads();
        if (c + 3 < 12) prefetch(c + 3, st);
        CP_COMMIT();
        st = (st == 2) ? 0 : st + 1;
    }

    int r0 = tile * 128 + wm * 32 + (lane >> 2);
    int cb = wn * 64 + (lane & 3) * 2;

    if (pooled == nullptr) {
        // store relu(out + bias) rows
        #pragma unroll
        for (int mt = 0; mt < 2; mt++) {
            #pragma unroll
            for (int nt = 0; nt < 8; nt++) {
                int col = cb + nt * 8;
                int row = r0 + mt * 16;
                float bx = bias[col], by = bias[col + 1];
                float2 v;
                v.x = fmaxf(acc[mt][nt][0] + bx, 0.f);
                v.y = fmaxf(acc[mt][nt][1] + by, 0.f);
                *(float2*)&yout[(size_t)row * HD + col] = v;
                v.x = fmaxf(acc[mt][nt][2] + bx, 0.f);
                v.y = fmaxf(acc[mt][nt][3] + by, 0.f);
                *(float2*)&yout[(size_t)(row + 8) * HD + col] = v;
            }
        }
    } else {
        // fused segment-sum pooling: a 128-row tile spans <= 2 graph segments
        __syncthreads();                    // smem pipeline no longer needed
        float* pb = (float*)smem;           // [2][128]
        pb[tid] = 0.f;                      // 256 threads zero 256 slots
        __syncthreads();
        const int gstart = (tile * 128) / SEG;
        #pragma unroll
        for (int mt = 0; mt < 2; mt++) {
            #pragma unroll
            for (int nt = 0; nt < 8; nt++) {
                int col = cb + nt * 8;
                int row = r0 + mt * 16;
                float bx = bias[col], by = bias[col + 1];
                int i0 = ((row / SEG) - gstart) << 7;
                int i1 = (((row + 8) / SEG) - gstart) << 7;
                atomicAdd(&pb[i0 + col],     fmaxf(acc[mt][nt][0] + bx, 0.f));
                atomicAdd(&pb[i0 + col + 1], fmaxf(acc[mt][nt][1] + by, 0.f));
                atomicAdd(&pb[i1 + col],     fmaxf(acc[mt][nt][2] + bx, 0.f));
                atomicAdd(&pb[i1 + col + 1], fmaxf(acc[mt][nt][3] + by, 0.f));
            }
        }
        __syncthreads();
        int g = gstart + (tid >> 7);
        if (g < NG) atomicAdd(&pooled[g * HD + (tid & 127)], pb[tid]);
    }
}

// ---------------- mixup: writes fp32 x + bf16 hi/lo ------------------------
__global__ void mixup_kernel(const float* __restrict__ lam, int which,
                             const float* __restrict__ yin) {
    int warp = (blockIdx.x * blockDim.x + threadIdx.x) >> 5;
    if (warp >= NN) return;
    int lane = threadIdx.x & 31;
    const int* perm = which ? g_p2 : g_p1;
    int p = perm[warp];
    float l = lam[0];
    float4 a = *(const float4*)&yin[(size_t)warp * HD + lane * 4];
    float4 b = *(const float4*)&yin[(size_t)p * HD + lane * 4];
    float4 o;
    o.x = l * a.x + (1.f - l) * b.x;
    o.y = l * a.y + (1.f - l) * b.y;
    o.z = l * a.z + (1.f - l) * b.z;
    o.w = l * a.w + (1.f - l) * b.w;
    *(float4*)&g_x[(size_t)warp * HD + lane * 4] = o;
    write_hilo(g_xh, g_xl, warp, lane, o);
}

// ---------------- head -----------------------------------------------------
__global__ void head_kernel(const float* __restrict__ Wl,
                            const float* __restrict__ bl,
                            float* __restrict__ out) {
    int g = blockIdx.x;
    int lane = threadIdx.x;
    float pv[4];
    #pragma unroll
    for (int q = 0; q < 4; q++) pv[q] = g_pooled[g * HD + lane + q * 32];
    float logits[OUTC];
    #pragma unroll
    for (int o = 0; o < OUTC; o++) {
        float s = 0.f;
        #pragma unroll
        for (int q = 0; q < 4; q++)
            s += pv[q] * Wl[(lane + q * 32) * OUTC + o];
        #pragma unroll
        for (int off = 16; off; off >>= 1)
            s += __shfl_down_sync(0xffffffffu, s, off);
        logits[o] = s;
    }
    if (lane == 0) {
        float m = -1e30f;
        #pragma unroll
        for (int o = 0; o < OUTC; o++) {
            logits[o] += bl[o];
            m = fmaxf(m, logits[o]);
        }
        float se = 0.f;
        #pragma unroll
        for (int o = 0; o < OUTC; o++) se += expf(logits[o] - m);
        float lse = m + logf(se);
        #pragma unroll
        for (int o = 0; o < OUTC; o++) out[g * OUTC + o] = logits[o] - lse;
    }
}

// ---------------- launch ----------------------------------------------------
extern "C" void kernel_launch(void* const* d_in, const int* in_sizes, int n_in,
                              void* d_out, int out_size) {
    const float* x0      = (const float*)d_in[0];
    const void*  eidx    = d_in[1];
    const float* lam     = (const float*)d_in[2];
    const void*  perm1   = d_in[5];
    const void*  perm2   = d_in[6];
    const float* W1_rel  = (const float*)d_in[8];
    const float* b1_rel  = (const float*)d_in[9];
    const float* W1_root = (const float*)d_in[10];
    const float* W2_rel  = (const float*)d_in[11];
    const float* b2_rel  = (const float*)d_in[12];
    const float* W2_root = (const float*)d_in[13];
    const float* W_lin   = (const float*)d_in[14];
    const float* b_lin   = (const float*)d_in[15];
    float* out = (float*)d_out;

    const int GEMM_SMEM = 3 * 32768;
    static int smem_set = 0;
    if (!smem_set) {
        cudaFuncSetAttribute(gemm_kernel, cudaFuncAttributeMaxDynamicSharedMemorySize,
                             GEMM_SMEM);
        smem_set = 1;
    }

    init_kernel<<<(NN + 255) / 256, 256>>>((const unsigned*)eidx);
    convhist_kernel<<<(NE + 255) / 256, 256>>>(eidx, perm1, perm2);
    scan_kernel<<<1, 1024>>>();
    scatter_kernel<<<(NE + 255) / 256, 256>>>();

    wprep_kernel<<<4, 128>>>(W1_root, W1_rel, W2_root, W2_rel);
    conv0_kernel<<<(NN * 32 + 255) / 256, 256>>>(x0);

    __nv_bfloat16 *xh, *xl, *ah, *al, *w;
    float *gx, *gy, *gp;
    cudaGetSymbolAddress((void**)&xh, g_xh);
    cudaGetSymbolAddress((void**)&xl, g_xl);
    cudaGetSymbolAddress((void**)&ah, g_ah);
    cudaGetSymbolAddress((void**)&al, g_al);
    cudaGetSymbolAddress((void**)&w,  g_w);
    cudaGetSymbolAddress((void**)&gx, g_x);
    cudaGetSymbolAddress((void**)&gy, g_y);
    cudaGetSymbolAddress((void**)&gp, g_pooled);
    __nv_bfloat16* w0rh = w + 0 * HD * HD;  __nv_bfloat16* w0rl = w + 1 * HD * HD;
    __nv_bfloat16* w0eh = w + 2 * HD * HD;  __nv_bfloat16* w0el = w + 3 * HD * HD;
    __nv_bfloat16* w1rh = w + 4 * HD * HD;  __nv_bfloat16* w1rl = w + 5 * HD * HD;
    __nv_bfloat16* w1eh = w + 6 * HD * HD;  __nv_bfloat16* w1el = w + 7 * HD * HD;

    // Layer 1
    agg_kernel<<<(NN * 32 + 255) / 256, 256>>>(x0);
    gemm_kernel<<<NT, 256, GEMM_SMEM>>>(xh, xl, ah, al, w0rh, w0rl, w0eh, w0el,
                                        b1_rel, gy, nullptr);
    mixup_kernel<<<(NN * 32 + 255) / 256, 256>>>(lam, 0, gy);

    // Layer 2
    agg_kernel<<<(NN * 32 + 255) / 256, 256>>>(gx);
    gemm_kernel<<<NT, 256, GEMM_SMEM>>>(xh, xl, ah, al, w1rh, w1rl, w1eh, w1el,
                                        b2_rel, gy, nullptr);
    mixup_kernel<<<(NN * 32 + 255) / 256, 256>>>(lam, 1, gy);

    // Layer 3 (conv2 weights reused; mixup3 invariant under pooling)
    // -> fused pooling epilogue, no y store
    agg_kernel<<<(NN * 32 + 255) / 256, 256>>>(gx);
    gemm_kernel<<<NT, 256, GEMM_SMEM>>>(xh, xl, ah, al, w1rh, w1rl, w1eh, w1el,
                                        b2_rel, gy, gp);

    head_kernel<<<NG, 32>>>(W_lin, b_lin, out);
}

// round 7
// speedup vs baseline: 1.4686x; 1.4686x over previous
#include <cuda_runtime.h>
#include <cuda_bf16.h>
#include <math.h>
#include <stdint.h>

#define NN 51200      // nodes
#define NE 819200     // edges
#define HD 128        // hidden / in dim
#define NG 128        // graphs
#define SEG 400       // nodes per graph
#define OUTC 10
#define NT  (NN / 128)          // 400 M-tiles

// ---------------- scratch (device globals) ---------------------------------
__device__ float g_x[NN * HD];     // fp32 features (agg gather source)
__device__ float g_y[NN * HD];     // conv output (post-relu)
__device__ __align__(16) __nv_bfloat16 g_xh[NN * HD];   // bf16 hi of x
__device__ __align__(16) __nv_bfloat16 g_xl[NN * HD];   // bf16 lo of x
__device__ __align__(16) __nv_bfloat16 g_ah[NN * HD];   // bf16 hi of agg
__device__ __align__(16) __nv_bfloat16 g_al[NN * HD];   // bf16 lo of agg
// weight images, transposed [n][k] bf16, row-major: 4 matrices x (hi,lo)
__device__ __align__(16) __nv_bfloat16 g_w[8 * HD * HD];
__device__ int   g_src[NE];
__device__ int   g_dst[NE];
__device__ int   g_p1[NN];
__device__ int   g_p2[NN];
__device__ int   g_cnt[NN];
__device__ int   g_rowstart[NN + 1];
__device__ int   g_cursor[NN];
__device__ int   g_eidx[NE];
__device__ float g_pooled[NG * HD];
__device__ int   g_is64;

// ---------------- helpers ---------------------------------------------------
__device__ __forceinline__ uint32_t smem_to_u32(const void* p) {
    uint32_t a;
    asm("{ .reg .u64 t; cvta.to.shared.u64 t, %1; cvt.u32.u64 %0, t; }"
        : "=r"(a) : "l"(p));
    return a;
}
#define CP_ASYNC16(dst, src) \
    asm volatile("cp.async.cg.shared.global [%0], [%1], 16;" \
                 :: "r"(dst), "l"(src) : "memory")
#define CP_COMMIT() asm volatile("cp.async.commit_group;" ::: "memory")
#define CP_WAIT2()  asm volatile("cp.async.wait_group 2;" ::: "memory")

__device__ __forceinline__ void ldsm_x4(uint32_t* r, uint32_t addr) {
    asm volatile("ldmatrix.sync.aligned.m8n8.x4.shared.b16 {%0,%1,%2,%3}, [%4];"
                 : "=r"(r[0]), "=r"(r[1]), "=r"(r[2]), "=r"(r[3]) : "r"(addr));
}
__device__ __forceinline__ void mma16816(float* c, const uint32_t* a, const uint32_t* b) {
    asm volatile("mma.sync.aligned.m16n8k16.row.col.f32.bf16.bf16.f32 "
                 "{%0,%1,%2,%3},{%4,%5,%6,%7},{%8,%9},{%0,%1,%2,%3};"
                 : "+f"(c[0]), "+f"(c[1]), "+f"(c[2]), "+f"(c[3])
                 : "r"(a[0]), "r"(a[1]), "r"(a[2]), "r"(a[3]), "r"(b[0]), "r"(b[1]));
}

__device__ __forceinline__ void write_hilo(__nv_bfloat16* hi, __nv_bfloat16* lo,
                                           int node, int lane, float4 v) {
    int off = node * HD + lane * 4;
    __nv_bfloat16 hx = __float2bfloat16_rn(v.x), hy = __float2bfloat16_rn(v.y);
    __nv_bfloat16 hz = __float2bfloat16_rn(v.z), hw = __float2bfloat16_rn(v.w);
    uint2 ph, pl;
    ph.x = (uint32_t)__bfloat16_as_ushort(hx) | ((uint32_t)__bfloat16_as_ushort(hy) << 16);
    ph.y = (uint32_t)__bfloat16_as_ushort(hz) | ((uint32_t)__bfloat16_as_ushort(hw) << 16);
    __nv_bfloat16 gx = __float2bfloat16_rn(v.x - __bfloat162float(hx));
    __nv_bfloat16 gy = __float2bfloat16_rn(v.y - __bfloat162float(hy));
    __nv_bfloat16 gz = __float2bfloat16_rn(v.z - __bfloat162float(hz));
    __nv_bfloat16 gw = __float2bfloat16_rn(v.w - __bfloat162float(hw));
    pl.x = (uint32_t)__bfloat16_as_ushort(gx) | ((uint32_t)__bfloat16_as_ushort(gy) << 16);
    pl.y = (uint32_t)__bfloat16_as_ushort(gz) | ((uint32_t)__bfloat16_as_ushort(gw) << 16);
    *(uint2*)&hi[off] = ph;
    *(uint2*)&lo[off] = pl;
}

// ---------------- init: zero counters/pooled + dtype detect ----------------
__global__ void init_kernel(const unsigned* __restrict__ e) {
    int i = blockIdx.x * blockDim.x + threadIdx.x;
    if (i < NN) g_cnt[i] = 0;
    if (i < NG * HD) g_pooled[i] = 0.0f;
    if (i == 0) {
        int all0 = 1;
        #pragma unroll 1
        for (int k = 0; k < 128; k++)
            if (e[2 * k + 1] != 0u) { all0 = 0; break; }
        g_is64 = all0;
    }
}

// fused convert + histogram
__global__ void convhist_kernel(const void* __restrict__ eraw,
                                const void* __restrict__ p1raw,
                                const void* __restrict__ p2raw) {
    int i = blockIdx.x * blockDim.x + threadIdx.x;
    const bool is64 = (g_is64 != 0);
    if (i < NE) {
        int s = is64 ? (int)((const long long*)eraw)[i] : ((const int*)eraw)[i];
        int d = is64 ? (int)((const long long*)eraw)[NE + i] : ((const int*)eraw)[NE + i];
        g_src[i] = s;
        g_dst[i] = d;
        atomicAdd(&g_cnt[d], 1);
    }
    if (i < NN) {
        g_p1[i] = is64 ? (int)((const long long*)p1raw)[i] : ((const int*)p1raw)[i];
        g_p2[i] = is64 ? (int)((const long long*)p2raw)[i] : ((const int*)p2raw)[i];
    }
}

// ---------------- single-block fused scan (NN = 1024 * 50) -----------------
__global__ void __launch_bounds__(1024)
scan_kernel() {
    const int t = threadIdx.x;
    const int base = t * 50;
    int sum = 0;
    #pragma unroll 1
    for (int i = 0; i < 50; i++) sum += g_cnt[base + i];

    const int lane = t & 31, warp = t >> 5;
    int v = sum;
    #pragma unroll
    for (int off = 1; off < 32; off <<= 1) {
        int n = __shfl_up_sync(0xffffffffu, v, off);
        if (lane >= off) v += n;
    }
    __shared__ int ws[32];
    if (lane == 31) ws[warp] = v;
    __syncthreads();
    if (warp == 0) {
        int w = ws[lane];
        #pragma unroll
        for (int off = 1; off < 32; off <<= 1) {
            int n = __shfl_up_sync(0xffffffffu, w, off);
            if (lane >= off) w += n;
        }
        ws[lane] = w;
    }
    __syncthreads();
    int offset = (warp == 0) ? 0 : ws[warp - 1];
    int run = offset + v - sum;

    #pragma unroll 1
    for (int i = 0; i < 50; i++) {
        g_rowstart[base + i] = run;
        g_cursor[base + i] = run;
        run += g_cnt[base + i];
    }
    if (t == 1023) g_rowstart[NN] = run;
}

__global__ void scatter_kernel() {
    int e = blockIdx.x * blockDim.x + threadIdx.x;
    if (e < NE) {
        int pos = atomicAdd(&g_cursor[g_dst[e]], 1);
        g_eidx[pos] = g_src[e];
    }
}

// ---------------- one-time bf16 hi/lo conversion of x0 ---------------------
__global__ void conv0_kernel(const float* __restrict__ xin) {
    int warp = (blockIdx.x * blockDim.x + threadIdx.x) >> 5;
    if (warp >= NN) return;
    int lane = threadIdx.x & 31;
    float4 v = *(const float4*)&xin[(size_t)warp * HD + lane * 4];
    write_hilo(g_xh, g_xl, warp, lane, v);
}

// ---------------- weight prep: transpose + bf16 split ----------------------
__global__ void wprep_kernel(const float* __restrict__ W0r,
                             const float* __restrict__ W0e,
                             const float* __restrict__ W1r,
                             const float* __restrict__ W1e) {
    const float* Ws[4] = {W0r, W0e, W1r, W1e};
    const float* W = Ws[blockIdx.x];
    __nv_bfloat16* hi = g_w + (size_t)(2 * blockIdx.x) * HD * HD;
    __nv_bfloat16* lo = g_w + (size_t)(2 * blockIdx.x + 1) * HD * HD;
    int n = threadIdx.x;
    for (int k0 = 0; k0 < HD; k0 += 4) {
        float4 v;
        v.x = W[(k0 + 0) * HD + n];
        v.y = W[(k0 + 1) * HD + n];
        v.z = W[(k0 + 2) * HD + n];
        v.w = W[(k0 + 3) * HD + n];
        int off = n * HD + k0;
        __nv_bfloat16 hx = __float2bfloat16_rn(v.x), hy = __float2bfloat16_rn(v.y);
        __nv_bfloat16 hz = __float2bfloat16_rn(v.z), hw = __float2bfloat16_rn(v.w);
        uint2 ph, pl;
        ph.x = (uint32_t)__bfloat16_as_ushort(hx) | ((uint32_t)__bfloat16_as_ushort(hy) << 16);
        ph.y = (uint32_t)__bfloat16_as_ushort(hz) | ((uint32_t)__bfloat16_as_ushort(hw) << 16);
        __nv_bfloat16 gx = __float2bfloat16_rn(v.x - __bfloat162float(hx));
        __nv_bfloat16 gy = __float2bfloat16_rn(v.y - __bfloat162float(hy));
        __nv_bfloat16 gz = __float2bfloat16_rn(v.z - __bfloat162float(hz));
        __nv_bfloat16 gw = __float2bfloat16_rn(v.w - __bfloat162float(hw));
        pl.x = (uint32_t)__bfloat16_as_ushort(gx) | ((uint32_t)__bfloat16_as_ushort(gy) << 16);
        pl.y = (uint32_t)__bfloat16_as_ushort(gz) | ((uint32_t)__bfloat16_as_ushort(gw) << 16);
        *(uint2*)&hi[off] = ph;
        *(uint2*)&lo[off] = pl;
    }
}

// ---------------- aggregation: warp/node, unroll-4, emits bf16 hi/lo -------
__global__ void agg_kernel(const float* __restrict__ xin) {
    int warp = (blockIdx.x * blockDim.x + threadIdx.x) >> 5;
    if (warp >= NN) return;
    int lane = threadIdx.x & 31;
    int s = g_rowstart[warp];
    int e = g_rowstart[warp + 1];
    float4 acc = make_float4(0.f, 0.f, 0.f, 0.f);
    int j = s;
    for (; j + 3 < e; j += 4) {
        int u0 = g_eidx[j],     u1 = g_eidx[j + 1];
        int u2 = g_eidx[j + 2], u3 = g_eidx[j + 3];
        float4 v0 = *(const float4*)&xin[(size_t)u0 * HD + lane * 4];
        float4 v1 = *(const float4*)&xin[(size_t)u1 * HD + lane * 4];
        float4 v2 = *(const float4*)&xin[(size_t)u2 * HD + lane * 4];
        float4 v3 = *(const float4*)&xin[(size_t)u3 * HD + lane * 4];
        acc.x += (v0.x + v1.x) + (v2.x + v3.x);
        acc.y += (v0.y + v1.y) + (v2.y + v3.y);
        acc.z += (v0.z + v1.z) + (v2.z + v3.z);
        acc.w += (v0.w + v1.w) + (v2.w + v3.w);
    }
    for (; j < e; j++) {
        int u = g_eidx[j];
        float4 v = *(const float4*)&xin[(size_t)u * HD + lane * 4];
        acc.x += v.x; acc.y += v.y; acc.z += v.z; acc.w += v.w;
    }
    write_hilo(g_ah, g_al, warp, lane, acc);
}

// ---------------- HMMA GEMM: y = relu([x|agg] @ [Wroot;Wrel] + b) ----------
// template<POOL>: two SEPARATE instantiations so the pooling epilogue's
// register pressure cannot perturb the store-path mainloop (R5 regression).
template <bool POOL>
__device__ __forceinline__ void
gemm_body(const __nv_bfloat16* __restrict__ xh, const __nv_bfloat16* __restrict__ xl,
          const __nv_bfloat16* __restrict__ ah, const __nv_bfloat16* __restrict__ al,
          const __nv_bfloat16* __restrict__ wrh, const __nv_bfloat16* __restrict__ wrl,
          const __nv_bfloat16* __restrict__ weh, const __nv_bfloat16* __restrict__ wel,
          const float* __restrict__ bias, float* __restrict__ yout,
          float* __restrict__ pooled) {
    extern __shared__ char smem[];
    __shared__ const uint4* Atab[6];
    __shared__ const uint4* Btab[6];
    const int tid = threadIdx.x, lane = tid & 31, wid = tid >> 5;
    const int wm = wid >> 1, wn = wid & 1;
    const int tile = blockIdx.x;

    if (tid == 0) {
        size_t toff = (size_t)tile * 128 * HD;
        Atab[0] = (const uint4*)(xh + toff); Atab[1] = (const uint4*)(ah + toff);
        Atab[2] = (const uint4*)(xl + toff); Atab[3] = (const uint4*)(al + toff);
        Atab[4] = Atab[0];                   Atab[5] = Atab[1];
        Btab[0] = (const uint4*)wrh; Btab[1] = (const uint4*)weh;
        Btab[2] = (const uint4*)wrh; Btab[3] = (const uint4*)weh;
        Btab[4] = (const uint4*)wrl; Btab[5] = (const uint4*)wel;
    }
    __syncthreads();
    const uint32_t sbase = smem_to_u32(smem);

    auto prefetch = [&](int cc, int st) {
        int seg = cc >> 1, ko4 = (cc & 1) << 3;
        const uint4* As = Atab[seg];
        const uint4* Bs = Btab[seg];
        uint32_t sA = sbase + st * 32768;
        uint32_t sB = sA + 16384;
        #pragma unroll
        for (int i = 0; i < 4; i++) {
            int idx = tid + 256 * i;
            int row = idx >> 3, c4 = idx & 7;
            int sw = (row * 8 + (c4 ^ (row & 7))) * 16;
            CP_ASYNC16(sA + sw, As + row * 16 + ko4 + c4);
            CP_ASYNC16(sB + sw, Bs + row * 16 + ko4 + c4);
        }
    };

    prefetch(0, 0); CP_COMMIT();
    prefetch(1, 1); CP_COMMIT();
    prefetch(2, 2); CP_COMMIT();

    float acc[2][8][4] = {};
    int st = 0;
    #pragma unroll 1
    for (int c = 0; c < 12; c++) {
        CP_WAIT2();
        __syncthreads();
        uint32_t sA = sbase + st * 32768;
        uint32_t sB = sA + 16384;
        #pragma unroll
        for (int kk = 0; kk < 4; kk++) {
            uint32_t a0[4], a1[4];
            {
                int row = wm * 32 + (lane & 15);
                int c4 = kk * 2 + (lane >> 4);
                ldsm_x4(a0, sA + (row * 8 + (c4 ^ (row & 7))) * 16);
                int row1 = row + 16;
                ldsm_x4(a1, sA + (row1 * 8 + (c4 ^ (row1 & 7))) * 16);
            }
            uint32_t b[4][4];
            #pragma unroll
            for (int p = 0; p < 4; p++) {
                int nrow = wn * 64 + p * 16 + ((lane >> 4) << 3) + (lane & 7);
                int c4 = kk * 2 + ((lane >> 3) & 1);
                ldsm_x4(b[p], sB + (nrow * 8 + (c4 ^ (nrow & 7))) * 16);
            }
            #pragma unroll
            for (int nt = 0; nt < 8; nt++) {
                mma16816(acc[0][nt], a0, &b[nt >> 1][(nt & 1) * 2]);
                mma16816(acc[1][nt], a1, &b[nt >> 1][(nt & 1) * 2]);
            }
        }
        __syncthreads();
        if (c + 3 < 12) prefetch(c + 3, st);
        CP_COMMIT();
        st = (st == 2) ? 0 : st + 1;
    }

    int r0 = tile * 128 + wm * 32 + (lane >> 2);
    int cb = wn * 64 + (lane & 3) * 2;

    if (!POOL) {
        #pragma unroll
        for (int mt = 0; mt < 2; mt++) {
            #pragma unroll
            for (int nt = 0; nt < 8; nt++) {
                int col = cb + nt * 8;
                int row = r0 + mt * 16;
                float bx = bias[col], by = bias[col + 1];
                float2 v;
                v.x = fmaxf(acc[mt][nt][0] + bx, 0.f);
                v.y = fmaxf(acc[mt][nt][1] + by, 0.f);
                *(float2*)&yout[(size_t)row * HD + col] = v;
                v.x = fmaxf(acc[mt][nt][2] + bx, 0.f);
                v.y = fmaxf(acc[mt][nt][3] + by, 0.f);
                *(float2*)&yout[(size_t)(row + 8) * HD + col] = v;
            }
        }
    } else {
        // fused segment-sum pooling: a 128-row tile spans <= 2 graph segments
        __syncthreads();
        float* pb = (float*)smem;           // [2][128]
        pb[tid] = 0.f;
        __syncthreads();
        const int gstart = (tile * 128) / SEG;
        #pragma unroll
        for (int mt = 0; mt < 2; mt++) {
            #pragma unroll
            for (int nt = 0; nt < 8; nt++) {
                int col = cb + nt * 8;
                int row = r0 + mt * 16;
                float bx = bias[col], by = bias[col + 1];
                int i0 = ((row / SEG) - gstart) << 7;
                int i1 = (((row + 8) / SEG) - gstart) << 7;
                atomicAdd(&pb[i0 + col],     fmaxf(acc[mt][nt][0] + bx, 0.f));
                atomicAdd(&pb[i0 + col + 1], fmaxf(acc[mt][nt][1] + by, 0.f));
                atomicAdd(&pb[i1 + col],     fmaxf(acc[mt][nt][2] + bx, 0.f));
                atomicAdd(&pb[i1 + col + 1], fmaxf(acc[mt][nt][3] + by, 0.f));
            }
        }
        __syncthreads();
        int g = gstart + (tid >> 7);
        if (g < NG) atomicAdd(&pooled[g * HD + (tid & 127)], pb[tid]);
    }
}

__global__ void __launch_bounds__(256, 2)
gemm_store_kernel(const __nv_bfloat16* xh, const __nv_bfloat16* xl,
                  const __nv_bfloat16* ah, const __nv_bfloat16* al,
                  const __nv_bfloat16* wrh, const __nv_bfloat16* wrl,
                  const __nv_bfloat16* weh, const __nv_bfloat16* wel,
                  const float* bias, float* yout) {
    gemm_body<false>(xh, xl, ah, al, wrh, wrl, weh, wel, bias, yout, nullptr);
}

__global__ void __launch_bounds__(256)
gemm_pool_kernel(const __nv_bfloat16* xh, const __nv_bfloat16* xl,
                 const __nv_bfloat16* ah, const __nv_bfloat16* al,
                 const __nv_bfloat16* wrh, const __nv_bfloat16* wrl,
                 const __nv_bfloat16* weh, const __nv_bfloat16* wel,
                 const float* bias, float* pooled) {
    gemm_body<true>(xh, xl, ah, al, wrh, wrl, weh, wel, bias, nullptr, pooled);
}

// ---------------- mixup: writes fp32 x + bf16 hi/lo ------------------------
__global__ void mixup_kernel(const float* __restrict__ lam, int which,
                             const float* __restrict__ yin) {
    int warp = (blockIdx.x * blockDim.x + threadIdx.x) >> 5;
    if (warp >= NN) return;
    int lane = threadIdx.x & 31;
    const int* perm = which ? g_p2 : g_p1;
    int p = perm[warp];
    float l = lam[0];
    float4 a = *(const float4*)&yin[(size_t)warp * HD + lane * 4];
    float4 b = *(const float4*)&yin[(size_t)p * HD + lane * 4];
    float4 o;
    o.x = l * a.x + (1.f - l) * b.x;
    o.y = l * a.y + (1.f - l) * b.y;
    o.z = l * a.z + (1.f - l) * b.z;
    o.w = l * a.w + (1.f - l) * b.w;
    *(float4*)&g_x[(size_t)warp * HD + lane * 4] = o;
    write_hilo(g_xh, g_xl, warp, lane, o);
}

// ---------------- head -----------------------------------------------------
__global__ void head_kernel(const float* __restrict__ Wl,
                            const float* __restrict__ bl,
                            float* __restrict__ out) {
    int g = blockIdx.x;
    int lane = threadIdx.x;
    float pv[4];
    #pragma unroll
    for (int q = 0; q < 4; q++) pv[q] = g_pooled[g * HD + lane + q * 32];
    float logits[OUTC];
    #pragma unroll
    for (int o = 0; o < OUTC; o++) {
        float s = 0.f;
        #pragma unroll
        for (int q = 0; q < 4; q++)
            s += pv[q] * Wl[(lane + q * 32) * OUTC + o];
        #pragma unroll
        for (int off = 16; off; off >>= 1)
            s += __shfl_down_sync(0xffffffffu, s, off);
        logits[o] = s;
    }
    if (lane == 0) {
        float m = -1e30f;
        #pragma unroll
        for (int o = 0; o < OUTC; o++) {
            logits[o] += bl[o];
            m = fmaxf(m, logits[o]);
        }
        float se = 0.f;
        #pragma unroll
        for (int o = 0; o < OUTC; o++) se += expf(logits[o] - m);
        float lse = m + logf(se);
        #pragma unroll
        for (int o = 0; o < OUTC; o++) out[g * OUTC + o] = logits[o] - lse;
    }
}

// ---------------- launch ----------------------------------------------------
extern "C" void kernel_launch(void* const* d_in, const int* in_sizes, int n_in,
                              void* d_out, int out_size) {
    const float* x0      = (const float*)d_in[0];
    const void*  eidx    = d_in[1];
    const float* lam     = (const float*)d_in[2];
    const void*  perm1   = d_in[5];
    const void*  perm2   = d_in[6];
    const float* W1_rel  = (const float*)d_in[8];
    const float* b1_rel  = (const float*)d_in[9];
    const float* W1_root = (const float*)d_in[10];
    const float* W2_rel  = (const float*)d_in[11];
    const float* b2_rel  = (const float*)d_in[12];
    const float* W2_root = (const float*)d_in[13];
    const float* W_lin   = (const float*)d_in[14];
    const float* b_lin   = (const float*)d_in[15];
    float* out = (float*)d_out;

    const int GEMM_SMEM = 3 * 32768;
    static int smem_set = 0;
    if (!smem_set) {
        cudaFuncSetAttribute(gemm_store_kernel,
                             cudaFuncAttributeMaxDynamicSharedMemorySize, GEMM_SMEM);
        cudaFuncSetAttribute(gemm_pool_kernel,
                             cudaFuncAttributeMaxDynamicSharedMemorySize, GEMM_SMEM);
        smem_set = 1;
    }

    init_kernel<<<(NN + 255) / 256, 256>>>((const unsigned*)eidx);
    convhist_kernel<<<(NE + 255) / 256, 256>>>(eidx, perm1, perm2);
    scan_kernel<<<1, 1024>>>();
    scatter_kernel<<<(NE + 255) / 256, 256>>>();

    wprep_kernel<<<4, 128>>>(W1_root, W1_rel, W2_root, W2_rel);
    conv0_kernel<<<(NN * 32 + 255) / 256, 256>>>(x0);

    __nv_bfloat16 *xh, *xl, *ah, *al, *w;
    float *gx, *gy, *gp;
    cudaGetSymbolAddress((void**)&xh, g_xh);
    cudaGetSymbolAddress((void**)&xl, g_xl);
    cudaGetSymbolAddress((void**)&ah, g_ah);
    cudaGetSymbolAddress((void**)&al, g_al);
    cudaGetSymbolAddress((void**)&w,  g_w);
    cudaGetSymbolAddress((void**)&gx, g_x);
    cudaGetSymbolAddress((void**)&gy, g_y);
    cudaGetSymbolAddress((void**)&gp, g_pooled);
    __nv_bfloat16* w0rh = w + 0 * HD * HD;  __nv_bfloat16* w0rl = w + 1 * HD * HD;
    __nv_bfloat16* w0eh = w + 2 * HD * HD;  __nv_bfloat16* w0el = w + 3 * HD * HD;
    __nv_bfloat16* w1rh = w + 4 * HD * HD;  __nv_bfloat16* w1rl = w + 5 * HD * HD;
    __nv_bfloat16* w1eh = w + 6 * HD * HD;  __nv_bfloat16* w1el = w + 7 * HD * HD;

    // Layer 1
    agg_kernel<<<(NN * 32 + 255) / 256, 256>>>(x0);
    gemm_store_kernel<<<NT, 256, GEMM_SMEM>>>(xh, xl, ah, al,
                                              w0rh, w0rl, w0eh, w0el, b1_rel, gy);
    mixup_kernel<<<(NN * 32 + 255) / 256, 256>>>(lam, 0, gy);

    // Layer 2
    agg_kernel<<<(NN * 32 + 255) / 256, 256>>>(gx);
    gemm_store_kernel<<<NT, 256, GEMM_SMEM>>>(xh, xl, ah, al,
                                              w1rh, w1rl, w1eh, w1el, b2_rel, gy);
    mixup_kernel<<<(NN * 32 + 255) / 256, 256>>>(lam, 1, gy);

    // Layer 3 (conv2 weights reused; mixup3 invariant under pooling)
    agg_kernel<<<(NN * 32 + 255) / 256, 256>>>(gx);
    gemm_pool_kernel<<<NT, 256, GEMM_SMEM>>>(xh, xl, ah, al,
                                             w1rh, w1rl, w1eh, w1el, b2_rel, gp);

    head_kernel<<<NG, 32>>>(W_lin, b_lin, out);
}

// round 8
// speedup vs baseline: 1.7999x; 1.2256x over previous
#include <cuda_runtime.h>
#include <cuda_bf16.h>
#include <math.h>
#include <stdint.h>

#define NN 51200      // nodes
#define NE 819200     // edges
#define HD 128        // hidden / in dim
#define NG 128        // graphs
#define SEG 400       // nodes per graph
#define OUTC 10
#define NT  (NN / 128)          // 400 M-tiles

// ---------------- scratch (device globals) ---------------------------------
__device__ float g_x[NN * HD];     // fp32 features (agg gather source)
__device__ float g_y[NN * HD];     // conv output (post-relu)
__device__ __align__(16) __nv_bfloat16 g_xh[NN * HD];   // bf16 hi of x
__device__ __align__(16) __nv_bfloat16 g_xl[NN * HD];   // bf16 lo of x
__device__ __align__(16) __nv_bfloat16 g_ah[NN * HD];   // bf16 hi of agg
__device__ __align__(16) __nv_bfloat16 g_al[NN * HD];   // bf16 lo of agg
__device__ __align__(16) __nv_bfloat16 g_w[8 * HD * HD];
__device__ int   g_src[NE];
__device__ int   g_dst[NE];
__device__ int   g_p1[NN];
__device__ int   g_p2[NN];
__device__ int   g_cnt[NN];
__device__ int   g_scanL[NN];
__device__ int   g_bsum[256];
__device__ int   g_boff[256];
__device__ int   g_rowstart[NN + 1];
__device__ int   g_cursor[NN];
__device__ int   g_eidx[NE];
__device__ float g_pooled[NG * HD];
__device__ int   g_is64;

// ---------------- helpers ---------------------------------------------------
__device__ __forceinline__ uint32_t smem_to_u32(const void* p) {
    uint32_t a;
    asm("{ .reg .u64 t; cvta.to.shared.u64 t, %1; cvt.u32.u64 %0, t; }"
        : "=r"(a) : "l"(p));
    return a;
}
#define CP_ASYNC16(dst, src) \
    asm volatile("cp.async.cg.shared.global [%0], [%1], 16;" \
                 :: "r"(dst), "l"(src) : "memory")
#define CP_COMMIT() asm volatile("cp.async.commit_group;" ::: "memory")
#define CP_WAIT2()  asm volatile("cp.async.wait_group 2;" ::: "memory")

__device__ __forceinline__ void ldsm_x4(uint32_t* r, uint32_t addr) {
    asm volatile("ldmatrix.sync.aligned.m8n8.x4.shared.b16 {%0,%1,%2,%3}, [%4];"
                 : "=r"(r[0]), "=r"(r[1]), "=r"(r[2]), "=r"(r[3]) : "r"(addr));
}
__device__ __forceinline__ void mma16816(float* c, const uint32_t* a, const uint32_t* b) {
    asm volatile("mma.sync.aligned.m16n8k16.row.col.f32.bf16.bf16.f32 "
                 "{%0,%1,%2,%3},{%4,%5,%6,%7},{%8,%9},{%0,%1,%2,%3};"
                 : "+f"(c[0]), "+f"(c[1]), "+f"(c[2]), "+f"(c[3])
                 : "r"(a[0]), "r"(a[1]), "r"(a[2]), "r"(a[3]), "r"(b[0]), "r"(b[1]));
}

__device__ __forceinline__ void write_hilo(__nv_bfloat16* hi, __nv_bfloat16* lo,
                                           int node, int lane, float4 v) {
    int off = node * HD + lane * 4;
    __nv_bfloat16 hx = __float2bfloat16_rn(v.x), hy = __float2bfloat16_rn(v.y);
    __nv_bfloat16 hz = __float2bfloat16_rn(v.z), hw = __float2bfloat16_rn(v.w);
    uint2 ph, pl;
    ph.x = (uint32_t)__bfloat16_as_ushort(hx) | ((uint32_t)__bfloat16_as_ushort(hy) << 16);
    ph.y = (uint32_t)__bfloat16_as_ushort(hz) | ((uint32_t)__bfloat16_as_ushort(hw) << 16);
    __nv_bfloat16 gx = __float2bfloat16_rn(v.x - __bfloat162float(hx));
    __nv_bfloat16 gy = __float2bfloat16_rn(v.y - __bfloat162float(hy));
    __nv_bfloat16 gz = __float2bfloat16_rn(v.z - __bfloat162float(hz));
    __nv_bfloat16 gw = __float2bfloat16_rn(v.w - __bfloat162float(hw));
    pl.x = (uint32_t)__bfloat16_as_ushort(gx) | ((uint32_t)__bfloat16_as_ushort(gy) << 16);
    pl.y = (uint32_t)__bfloat16_as_ushort(gz) | ((uint32_t)__bfloat16_as_ushort(gw) << 16);
    *(uint2*)&hi[off] = ph;
    *(uint2*)&lo[off] = pl;
}

// ---------------- init: zero counters/pooled + dtype detect ----------------
__global__ void init_kernel(const unsigned* __restrict__ e) {
    int i = blockIdx.x * blockDim.x + threadIdx.x;
    if (i < NN) g_cnt[i] = 0;
    if (i < NG * HD) g_pooled[i] = 0.0f;
    if (i == 0) {
        int all0 = 1;
        #pragma unroll 1
        for (int k = 0; k < 128; k++)
            if (e[2 * k + 1] != 0u) { all0 = 0; break; }
        g_is64 = all0;
    }
}

// fused convert + histogram
__global__ void convhist_kernel(const void* __restrict__ eraw,
                                const void* __restrict__ p1raw,
                                const void* __restrict__ p2raw) {
    int i = blockIdx.x * blockDim.x + threadIdx.x;
    const bool is64 = (g_is64 != 0);
    if (i < NE) {
        int s = is64 ? (int)((const long long*)eraw)[i] : ((const int*)eraw)[i];
        int d = is64 ? (int)((const long long*)eraw)[NE + i] : ((const int*)eraw)[NE + i];
        g_src[i] = s;
        g_dst[i] = d;
        atomicAdd(&g_cnt[d], 1);
    }
    if (i < NN) {
        g_p1[i] = is64 ? (int)((const long long*)p1raw)[i] : ((const int*)p1raw)[i];
        g_p2[i] = is64 ? (int)((const long long*)p2raw)[i] : ((const int*)p2raw)[i];
    }
}

// ---------------- 3-kernel scan chain (R4-proven) ---------------------------
__global__ void scan1_kernel() {
    __shared__ int sh[256];
    int b = blockIdx.x, t = threadIdx.x;
    int i = b * 256 + t;
    int v = (i < NN) ? g_cnt[i] : 0;
    sh[t] = v;
    __syncthreads();
    #pragma unroll
    for (int off = 1; off < 256; off <<= 1) {
        int add = (t >= off) ? sh[t - off] : 0;
        __syncthreads();
        sh[t] += add;
        __syncthreads();
    }
    if (i < NN) g_scanL[i] = sh[t] - v;
    if (t == 255) g_bsum[b] = sh[255];
}

__global__ void scan2_kernel() {
    __shared__ int sh[256];
    int t = threadIdx.x;
    int v = (t < (NN + 255) / 256) ? g_bsum[t] : 0;
    sh[t] = v;
    __syncthreads();
    #pragma unroll
    for (int off = 1; off < 256; off <<= 1) {
        int add = (t >= off) ? sh[t - off] : 0;
        __syncthreads();
        sh[t] += add;
        __syncthreads();
    }
    g_boff[t] = sh[t] - v;
}

__global__ void scan3_kernel() {
    int i = blockIdx.x * blockDim.x + threadIdx.x;
    if (i < NN) {
        int rs = g_scanL[i] + g_boff[i >> 8];
        g_rowstart[i] = rs;
        g_cursor[i] = rs;
    }
    if (i == 0) g_rowstart[NN] = NE;
}

__global__ void scatter_kernel() {
    int e = blockIdx.x * blockDim.x + threadIdx.x;
    if (e < NE) {
        int pos = atomicAdd(&g_cursor[g_dst[e]], 1);
        g_eidx[pos] = g_src[e];
    }
}

// ---------------- one-time bf16 hi/lo conversion of x0 ---------------------
__global__ void conv0_kernel(const float* __restrict__ xin) {
    int warp = (blockIdx.x * blockDim.x + threadIdx.x) >> 5;
    if (warp >= NN) return;
    int lane = threadIdx.x & 31;
    float4 v = *(const float4*)&xin[(size_t)warp * HD + lane * 4];
    write_hilo(g_xh, g_xl, warp, lane, v);
}

// ---------------- weight prep: transpose + bf16 split ----------------------
__global__ void wprep_kernel(const float* __restrict__ W0r,
                             const float* __restrict__ W0e,
                             const float* __restrict__ W1r,
                             const float* __restrict__ W1e) {
    const float* Ws[4] = {W0r, W0e, W1r, W1e};
    const float* W = Ws[blockIdx.x];
    __nv_bfloat16* hi = g_w + (size_t)(2 * blockIdx.x) * HD * HD;
    __nv_bfloat16* lo = g_w + (size_t)(2 * blockIdx.x + 1) * HD * HD;
    int n = threadIdx.x;
    for (int k0 = 0; k0 < HD; k0 += 4) {
        float4 v;
        v.x = W[(k0 + 0) * HD + n];
        v.y = W[(k0 + 1) * HD + n];
        v.z = W[(k0 + 2) * HD + n];
        v.w = W[(k0 + 3) * HD + n];
        int off = n * HD + k0;
        __nv_bfloat16 hx = __float2bfloat16_rn(v.x), hy = __float2bfloat16_rn(v.y);
        __nv_bfloat16 hz = __float2bfloat16_rn(v.z), hw = __float2bfloat16_rn(v.w);
        uint2 ph, pl;
        ph.x = (uint32_t)__bfloat16_as_ushort(hx) | ((uint32_t)__bfloat16_as_ushort(hy) << 16);
        ph.y = (uint32_t)__bfloat16_as_ushort(hz) | ((uint32_t)__bfloat16_as_ushort(hw) << 16);
        __nv_bfloat16 gx = __float2bfloat16_rn(v.x - __bfloat162float(hx));
        __nv_bfloat16 gy = __float2bfloat16_rn(v.y - __bfloat162float(hy));
        __nv_bfloat16 gz = __float2bfloat16_rn(v.z - __bfloat162float(hz));
        __nv_bfloat16 gw = __float2bfloat16_rn(v.w - __bfloat162float(hw));
        pl.x = (uint32_t)__bfloat16_as_ushort(gx) | ((uint32_t)__bfloat16_as_ushort(gy) << 16);
        pl.y = (uint32_t)__bfloat16_as_ushort(gz) | ((uint32_t)__bfloat16_as_ushort(gw) << 16);
        *(uint2*)&hi[off] = ph;
        *(uint2*)&lo[off] = pl;
    }
}

// ---------------- aggregation: warp/node, unroll-2 (R4-proven) -------------
__global__ void agg_kernel(const float* __restrict__ xin) {
    int warp = (blockIdx.x * blockDim.x + threadIdx.x) >> 5;
    if (warp >= NN) return;
    int lane = threadIdx.x & 31;
    int s = g_rowstart[warp];
    int e = g_rowstart[warp + 1];
    float4 acc = make_float4(0.f, 0.f, 0.f, 0.f);
    int j = s;
    for (; j + 1 < e; j += 2) {
        int u0 = g_eidx[j], u1 = g_eidx[j + 1];
        float4 v0 = *(const float4*)&xin[(size_t)u0 * HD + lane * 4];
        float4 v1 = *(const float4*)&xin[(size_t)u1 * HD + lane * 4];
        acc.x += v0.x + v1.x; acc.y += v0.y + v1.y;
        acc.z += v0.z + v1.z; acc.w += v0.w + v1.w;
    }
    if (j < e) {
        int u = g_eidx[j];
        float4 v = *(const float4*)&xin[(size_t)u * HD + lane * 4];
        acc.x += v.x; acc.y += v.y; acc.z += v.z; acc.w += v.w;
    }
    write_hilo(g_ah, g_al, warp, lane, acc);
}

// ---------------- HMMA GEMM: y = relu([x|agg] @ [Wroot;Wrel] + b) ----------
template <bool POOL>
__device__ __forceinline__ void
gemm_body(const __nv_bfloat16* __restrict__ xh, const __nv_bfloat16* __restrict__ xl,
          const __nv_bfloat16* __restrict__ ah, const __nv_bfloat16* __restrict__ al,
          const __nv_bfloat16* __restrict__ wrh, const __nv_bfloat16* __restrict__ wrl,
          const __nv_bfloat16* __restrict__ weh, const __nv_bfloat16* __restrict__ wel,
          const float* __restrict__ bias, float* __restrict__ yout,
          float* __restrict__ pooled) {
    extern __shared__ char smem[];
    __shared__ const uint4* Atab[6];
    __shared__ const uint4* Btab[6];
    const int tid = threadIdx.x, lane = tid & 31, wid = tid >> 5;
    const int wm = wid >> 1, wn = wid & 1;
    const int tile = blockIdx.x;

    if (tid == 0) {
        size_t toff = (size_t)tile * 128 * HD;
        Atab[0] = (const uint4*)(xh + toff); Atab[1] = (const uint4*)(ah + toff);
        Atab[2] = (const uint4*)(xl + toff); Atab[3] = (const uint4*)(al + toff);
        Atab[4] = Atab[0];                   Atab[5] = Atab[1];
        Btab[0] = (const uint4*)wrh; Btab[1] = (const uint4*)weh;
        Btab[2] = (const uint4*)wrh; Btab[3] = (const uint4*)weh;
        Btab[4] = (const uint4*)wrl; Btab[5] = (const uint4*)wel;
    }
    __syncthreads();
    const uint32_t sbase = smem_to_u32(smem);

    auto prefetch = [&](int cc, int st) {
        int seg = cc >> 1, ko4 = (cc & 1) << 3;
        const uint4* As = Atab[seg];
        const uint4* Bs = Btab[seg];
        uint32_t sA = sbase + st * 32768;
        uint32_t sB = sA + 16384;
        #pragma unroll
        for (int i = 0; i < 4; i++) {
            int idx = tid + 256 * i;
            int row = idx >> 3, c4 = idx & 7;
            int sw = (row * 8 + (c4 ^ (row & 7))) * 16;
            CP_ASYNC16(sA + sw, As + row * 16 + ko4 + c4);
            CP_ASYNC16(sB + sw, Bs + row * 16 + ko4 + c4);
        }
    };

    prefetch(0, 0); CP_COMMIT();
    prefetch(1, 1); CP_COMMIT();
    prefetch(2, 2); CP_COMMIT();

    float acc[2][8][4] = {};
    int st = 0;
    #pragma unroll 1
    for (int c = 0; c < 12; c++) {
        CP_WAIT2();
        __syncthreads();
        uint32_t sA = sbase + st * 32768;
        uint32_t sB = sA + 16384;
        #pragma unroll
        for (int kk = 0; kk < 4; kk++) {
            uint32_t a0[4], a1[4];
            {
                int row = wm * 32 + (lane & 15);
                int c4 = kk * 2 + (lane >> 4);
                ldsm_x4(a0, sA + (row * 8 + (c4 ^ (row & 7))) * 16);
                int row1 = row + 16;
                ldsm_x4(a1, sA + (row1 * 8 + (c4 ^ (row1 & 7))) * 16);
            }
            uint32_t b[4][4];
            #pragma unroll
            for (int p = 0; p < 4; p++) {
                int nrow = wn * 64 + p * 16 + ((lane >> 4) << 3) + (lane & 7);
                int c4 = kk * 2 + ((lane >> 3) & 1);
                ldsm_x4(b[p], sB + (nrow * 8 + (c4 ^ (nrow & 7))) * 16);
            }
            #pragma unroll
            for (int nt = 0; nt < 8; nt++) {
                mma16816(acc[0][nt], a0, &b[nt >> 1][(nt & 1) * 2]);
                mma16816(acc[1][nt], a1, &b[nt >> 1][(nt & 1) * 2]);
            }
        }
        __syncthreads();
        if (c + 3 < 12) prefetch(c + 3, st);
        CP_COMMIT();
        st = (st == 2) ? 0 : st + 1;
    }

    int r0 = tile * 128 + wm * 32 + (lane >> 2);
    int cb = wn * 64 + (lane & 3) * 2;

    if (!POOL) {
        #pragma unroll
        for (int mt = 0; mt < 2; mt++) {
            #pragma unroll
            for (int nt = 0; nt < 8; nt++) {
                int col = cb + nt * 8;
                int row = r0 + mt * 16;
                float bx = bias[col], by = bias[col + 1];
                float2 v;
                v.x = fmaxf(acc[mt][nt][0] + bx, 0.f);
                v.y = fmaxf(acc[mt][nt][1] + by, 0.f);
                *(float2*)&yout[(size_t)row * HD + col] = v;
                v.x = fmaxf(acc[mt][nt][2] + bx, 0.f);
                v.y = fmaxf(acc[mt][nt][3] + by, 0.f);
                *(float2*)&yout[(size_t)(row + 8) * HD + col] = v;
            }
        }
    } else {
        // fused segment-sum pooling: a 128-row tile spans <= 2 graph segments
        __syncthreads();
        float* pb = (float*)smem;           // [2][128]
        pb[tid] = 0.f;
        __syncthreads();
        const int gstart = (tile * 128) / SEG;
        #pragma unroll
        for (int mt = 0; mt < 2; mt++) {
            #pragma unroll
            for (int nt = 0; nt < 8; nt++) {
                int col = cb + nt * 8;
                int row = r0 + mt * 16;
                float bx = bias[col], by = bias[col + 1];
                int i0 = ((row / SEG) - gstart) << 7;
                int i1 = (((row + 8) / SEG) - gstart) << 7;
                atomicAdd(&pb[i0 + col],     fmaxf(acc[mt][nt][0] + bx, 0.f));
                atomicAdd(&pb[i0 + col + 1], fmaxf(acc[mt][nt][1] + by, 0.f));
                atomicAdd(&pb[i1 + col],     fmaxf(acc[mt][nt][2] + bx, 0.f));
                atomicAdd(&pb[i1 + col + 1], fmaxf(acc[mt][nt][3] + by, 0.f));
            }
        }
        __syncthreads();
        int g = gstart + (tid >> 7);
        if (g < NG) atomicAdd(&pooled[g * HD + (tid & 127)], pb[tid]);
    }
}

__global__ void __launch_bounds__(256, 2)
gemm_store_kernel(const __nv_bfloat16* xh, const __nv_bfloat16* xl,
                  const __nv_bfloat16* ah, const __nv_bfloat16* al,
                  const __nv_bfloat16* wrh, const __nv_bfloat16* wrl,
                  const __nv_bfloat16* weh, const __nv_bfloat16* wel,
                  const float* bias, float* yout) {
    gemm_body<false>(xh, xl, ah, al, wrh, wrl, weh, wel, bias, yout, nullptr);
}

__global__ void __launch_bounds__(256, 2)
gemm_pool_kernel(const __nv_bfloat16* xh, const __nv_bfloat16* xl,
                 const __nv_bfloat16* ah, const __nv_bfloat16* al,
                 const __nv_bfloat16* wrh, const __nv_bfloat16* wrl,
                 const __nv_bfloat16* weh, const __nv_bfloat16* wel,
                 const float* bias, float* pooled) {
    gemm_body<true>(xh, xl, ah, al, wrh, wrl, weh, wel, bias, nullptr, pooled);
}

// ---------------- mixup: writes fp32 x + bf16 hi/lo ------------------------
__global__ void mixup_kernel(const float* __restrict__ lam, int which,
                             const float* __restrict__ yin) {
    int warp = (blockIdx.x * blockDim.x + threadIdx.x) >> 5;
    if (warp >= NN) return;
    int lane = threadIdx.x & 31;
    const int* perm = which ? g_p2 : g_p1;
    int p = perm[warp];
    float l = lam[0];
    float4 a = *(const float4*)&yin[(size_t)warp * HD + lane * 4];
    float4 b = *(const float4*)&yin[(size_t)p * HD + lane * 4];
    float4 o;
    o.x = l * a.x + (1.f - l) * b.x;
    o.y = l * a.y + (1.f - l) * b.y;
    o.z = l * a.z + (1.f - l) * b.z;
    o.w = l * a.w + (1.f - l) * b.w;
    *(float4*)&g_x[(size_t)warp * HD + lane * 4] = o;
    write_hilo(g_xh, g_xl, warp, lane, o);
}

// ---------------- head -----------------------------------------------------
__global__ void head_kernel(const float* __restrict__ Wl,
                            const float* __restrict__ bl,
                            float* __restrict__ out) {
    int g = blockIdx.x;
    int lane = threadIdx.x;
    float pv[4];
    #pragma unroll
    for (int q = 0; q < 4; q++) pv[q] = g_pooled[g * HD + lane + q * 32];
    float logits[OUTC];
    #pragma unroll
    for (int o = 0; o < OUTC; o++) {
        float s = 0.f;
        #pragma unroll
        for (int q = 0; q < 4; q++)
            s += pv[q] * Wl[(lane + q * 32) * OUTC + o];
        #pragma unroll
        for (int off = 16; off; off >>= 1)
            s += __shfl_down_sync(0xffffffffu, s, off);
        logits[o] = s;
    }
    if (lane == 0) {
        float m = -1e30f;
        #pragma unroll
        for (int o = 0; o < OUTC; o++) {
            logits[o] += bl[o];
            m = fmaxf(m, logits[o]);
        }
        float se = 0.f;
        #pragma unroll
        for (int o = 0; o < OUTC; o++) se += expf(logits[o] - m);
        float lse = m + logf(se);
        #pragma unroll
        for (int o = 0; o < OUTC; o++) out[g * OUTC + o] = logits[o] - lse;
    }
}

// ---------------- launch ----------------------------------------------------
extern "C" void kernel_launch(void* const* d_in, const int* in_sizes, int n_in,
                              void* d_out, int out_size) {
    const float* x0      = (const float*)d_in[0];
    const void*  eidx    = d_in[1];
    const float* lam     = (const float*)d_in[2];
    const void*  perm1   = d_in[5];
    const void*  perm2   = d_in[6];
    const float* W1_rel  = (const float*)d_in[8];
    const float* b1_rel  = (const float*)d_in[9];
    const float* W1_root = (const float*)d_in[10];
    const float* W2_rel  = (const float*)d_in[11];
    const float* b2_rel  = (const float*)d_in[12];
    const float* W2_root = (const float*)d_in[13];
    const float* W_lin   = (const float*)d_in[14];
    const float* b_lin   = (const float*)d_in[15];
    float* out = (float*)d_out;

    const int GEMM_SMEM = 3 * 32768;
    static int smem_set = 0;
    if (!smem_set) {
        cudaFuncSetAttribute(gemm_store_kernel,
                             cudaFuncAttributeMaxDynamicSharedMemorySize, GEMM_SMEM);
        cudaFuncSetAttribute(gemm_pool_kernel,
                             cudaFuncAttributeMaxDynamicSharedMemorySize, GEMM_SMEM);
        smem_set = 1;
    }

    init_kernel<<<(NN + 255) / 256, 256>>>((const unsigned*)eidx);
    convhist_kernel<<<(NE + 255) / 256, 256>>>(eidx, perm1, perm2);
    scan1_kernel<<<(NN + 255) / 256, 256>>>();
    scan2_kernel<<<1, 256>>>();
    scan3_kernel<<<(NN + 255) / 256, 256>>>();
    scatter_kernel<<<(NE + 255) / 256, 256>>>();

    wprep_kernel<<<4, 128>>>(W1_root, W1_rel, W2_root, W2_rel);
    conv0_kernel<<<(NN * 32 + 255) / 256, 256>>>(x0);

    __nv_bfloat16 *xh, *xl, *ah, *al, *w;
    float *gx, *gy, *gp;
    cudaGetSymbolAddress((void**)&xh, g_xh);
    cudaGetSymbolAddress((void**)&xl, g_xl);
    cudaGetSymbolAddress((void**)&ah, g_ah);
    cudaGetSymbolAddress((void**)&al, g_al);
    cudaGetSymbolAddress((void**)&w,  g_w);
    cudaGetSymbolAddress((void**)&gx, g_x);
    cudaGetSymbolAddress((void**)&gy, g_y);
    cudaGetSymbolAddress((void**)&gp, g_pooled);
    __nv_bfloat16* w0rh = w + 0 * HD * HD;  __nv_bfloat16* w0rl = w + 1 * HD * HD;
    __nv_bfloat16* w0eh = w + 2 * HD * HD;  __nv_bfloat16* w0el = w + 3 * HD * HD;
    __nv_bfloat16* w1rh = w + 4 * HD * HD;  __nv_bfloat16* w1rl = w + 5 * HD * HD;
    __nv_bfloat16* w1eh = w + 6 * HD * HD;  __nv_bfloat16* w1el = w + 7 * HD * HD;

    // Layer 1
    agg_kernel<<<(NN * 32 + 255) / 256, 256>>>(x0);
    gemm_store_kernel<<<NT, 256, GEMM_SMEM>>>(xh, xl, ah, al,
                                              w0rh, w0rl, w0eh, w0el, b1_rel, gy);
    mixup_kernel<<<(NN * 32 + 255) / 256, 256>>>(lam, 0, gy);

    // Layer 2
    agg_kernel<<<(NN * 32 + 255) / 256, 256>>>(gx);
    gemm_store_kernel<<<NT, 256, GEMM_SMEM>>>(xh, xl, ah, al,
                                              w1rh, w1rl, w1eh, w1el, b2_rel, gy);
    mixup_kernel<<<(NN * 32 + 255) / 256, 256>>>(lam, 1, gy);

    // Layer 3 (conv2 weights reused; mixup3 invariant under pooling)
    agg_kernel<<<(NN * 32 + 255) / 256, 256>>>(gx);
    gemm_pool_kernel<<<NT, 256, GEMM_SMEM>>>(xh, xl, ah, al,
                                             w1rh, w1rl, w1eh, w1el, b2_rel, gp);

    head_kernel<<<NG, 32>>>(W_lin, b_lin, out);
}

// round 9
// speedup vs baseline: 2.2339x; 1.2411x over previous
#include <cuda_runtime.h>
#include <cuda_bf16.h>
#include <math.h>
#include <stdint.h>

#define NN 51200      // nodes
#define NE 819200     // edges
#define HD 128        // hidden / in dim
#define NG 128        // graphs
#define SEG 400       // nodes per graph
#define OUTC 10
#define NT  (NN / 128)          // 400 M-tiles

// ---------------- scratch (device globals) ---------------------------------
__device__ float g_x[NN * HD];     // fp32 features (agg gather source)
__device__ float g_y[NN * HD];     // conv output (post-relu)
__device__ __align__(16) __nv_bfloat16 g_xh[NN * HD];   // bf16 hi of x
__device__ __align__(16) __nv_bfloat16 g_xl[NN * HD];   // bf16 lo of x
__device__ __align__(16) __nv_bfloat16 g_ah[NN * HD];   // bf16 hi of agg
__device__ __align__(16) __nv_bfloat16 g_al[NN * HD];   // bf16 lo of agg
__device__ __align__(16) __nv_bfloat16 g_w[8 * HD * HD];
__device__ int   g_src[NE];
__device__ int   g_dst[NE];
__device__ int   g_p1[NN];
__device__ int   g_p2[NN];
__device__ int   g_cnt[NN];
__device__ int   g_scanL[NN];
__device__ int   g_bsum[256];
__device__ int   g_boff[256];
__device__ int   g_rowstart[NN + 1];
__device__ int   g_cursor[NN];
__device__ int   g_eidx[NE];
__device__ float g_pooled[NG * HD];
__device__ int   g_is64;

// ---------------- helpers ---------------------------------------------------
__device__ __forceinline__ uint32_t smem_to_u32(const void* p) {
    uint32_t a;
    asm("{ .reg .u64 t; cvta.to.shared.u64 t, %1; cvt.u32.u64 %0, t; }"
        : "=r"(a) : "l"(p));
    return a;
}
#define CP_ASYNC16(dst, src) \
    asm volatile("cp.async.cg.shared.global [%0], [%1], 16;" \
                 :: "r"(dst), "l"(src) : "memory")
#define CP_COMMIT() asm volatile("cp.async.commit_group;" ::: "memory")
#define CP_WAIT2()  asm volatile("cp.async.wait_group 2;" ::: "memory")

__device__ __forceinline__ void ldsm_x4(uint32_t* r, uint32_t addr) {
    asm volatile("ldmatrix.sync.aligned.m8n8.x4.shared.b16 {%0,%1,%2,%3}, [%4];"
                 : "=r"(r[0]), "=r"(r[1]), "=r"(r[2]), "=r"(r[3]) : "r"(addr));
}
__device__ __forceinline__ void mma16816(float* c, const uint32_t* a, const uint32_t* b) {
    asm volatile("mma.sync.aligned.m16n8k16.row.col.f32.bf16.bf16.f32 "
                 "{%0,%1,%2,%3},{%4,%5,%6,%7},{%8,%9},{%0,%1,%2,%3};"
                 : "+f"(c[0]), "+f"(c[1]), "+f"(c[2]), "+f"(c[3])
                 : "r"(a[0]), "r"(a[1]), "r"(a[2]), "r"(a[3]), "r"(b[0]), "r"(b[1]));
}

__device__ __forceinline__ void write_hilo(__nv_bfloat16* hi, __nv_bfloat16* lo,
                                           int node, int lane, float4 v) {
    int off = node * HD + lane * 4;
    __nv_bfloat16 hx = __float2bfloat16_rn(v.x), hy = __float2bfloat16_rn(v.y);
    __nv_bfloat16 hz = __float2bfloat16_rn(v.z), hw = __float2bfloat16_rn(v.w);
    uint2 ph, pl;
    ph.x = (uint32_t)__bfloat16_as_ushort(hx) | ((uint32_t)__bfloat16_as_ushort(hy) << 16);
    ph.y = (uint32_t)__bfloat16_as_ushort(hz) | ((uint32_t)__bfloat16_as_ushort(hw) << 16);
    __nv_bfloat16 gx = __float2bfloat16_rn(v.x - __bfloat162float(hx));
    __nv_bfloat16 gy = __float2bfloat16_rn(v.y - __bfloat162float(hy));
    __nv_bfloat16 gz = __float2bfloat16_rn(v.z - __bfloat162float(hz));
    __nv_bfloat16 gw = __float2bfloat16_rn(v.w - __bfloat162float(hw));
    pl.x = (uint32_t)__bfloat16_as_ushort(gx) | ((uint32_t)__bfloat16_as_ushort(gy) << 16);
    pl.y = (uint32_t)__bfloat16_as_ushort(gz) | ((uint32_t)__bfloat16_as_ushort(gw) << 16);
    *(uint2*)&hi[off] = ph;
    *(uint2*)&lo[off] = pl;
}

// ---------------- init: zero counters/pooled + dtype detect ----------------
__global__ void init_kernel(const unsigned* __restrict__ e) {
    int i = blockIdx.x * blockDim.x + threadIdx.x;
    if (i < NN) g_cnt[i] = 0;
    if (i < NG * HD) g_pooled[i] = 0.0f;
    if (i == 0) {
        int all0 = 1;
        #pragma unroll 1
        for (int k = 0; k < 128; k++)
            if (e[2 * k + 1] != 0u) { all0 = 0; break; }
        g_is64 = all0;
    }
}

// fused convert + histogram
__global__ void convhist_kernel(const void* __restrict__ eraw,
                                const void* __restrict__ p1raw,
                                const void* __restrict__ p2raw) {
    int i = blockIdx.x * blockDim.x + threadIdx.x;
    const bool is64 = (g_is64 != 0);
    if (i < NE) {
        int s = is64 ? (int)((const long long*)eraw)[i] : ((const int*)eraw)[i];
        int d = is64 ? (int)((const long long*)eraw)[NE + i] : ((const int*)eraw)[NE + i];
        g_src[i] = s;
        g_dst[i] = d;
        atomicAdd(&g_cnt[d], 1);
    }
    if (i < NN) {
        g_p1[i] = is64 ? (int)((const long long*)p1raw)[i] : ((const int*)p1raw)[i];
        g_p2[i] = is64 ? (int)((const long long*)p2raw)[i] : ((const int*)p2raw)[i];
    }
}

// ---------------- 3-kernel scan chain (R4-proven) ---------------------------
__global__ void scan1_kernel() {
    __shared__ int sh[256];
    int b = blockIdx.x, t = threadIdx.x;
    int i = b * 256 + t;
    int v = (i < NN) ? g_cnt[i] : 0;
    sh[t] = v;
    __syncthreads();
    #pragma unroll
    for (int off = 1; off < 256; off <<= 1) {
        int add = (t >= off) ? sh[t - off] : 0;
        __syncthreads();
        sh[t] += add;
        __syncthreads();
    }
    if (i < NN) g_scanL[i] = sh[t] - v;
    if (t == 255) g_bsum[b] = sh[255];
}

__global__ void scan2_kernel() {
    __shared__ int sh[256];
    int t = threadIdx.x;
    int v = (t < (NN + 255) / 256) ? g_bsum[t] : 0;
    sh[t] = v;
    __syncthreads();
    #pragma unroll
    for (int off = 1; off < 256; off <<= 1) {
        int add = (t >= off) ? sh[t - off] : 0;
        __syncthreads();
        sh[t] += add;
        __syncthreads();
    }
    g_boff[t] = sh[t] - v;
}

__global__ void scan3_kernel() {
    int i = blockIdx.x * blockDim.x + threadIdx.x;
    if (i < NN) {
        int rs = g_scanL[i] + g_boff[i >> 8];
        g_rowstart[i] = rs;
        g_cursor[i] = rs;
    }
    if (i == 0) g_rowstart[NN] = NE;
}

__global__ void scatter_kernel() {
    int e = blockIdx.x * blockDim.x + threadIdx.x;
    if (e < NE) {
        int pos = atomicAdd(&g_cursor[g_dst[e]], 1);
        g_eidx[pos] = g_src[e];
    }
}

// ---------------- weight prep: transpose + bf16 split ----------------------
__global__ void wprep_kernel(const float* __restrict__ W0r,
                             const float* __restrict__ W0e,
                             const float* __restrict__ W1r,
                             const float* __restrict__ W1e) {
    const float* Ws[4] = {W0r, W0e, W1r, W1e};
    const float* W = Ws[blockIdx.x];
    __nv_bfloat16* hi = g_w + (size_t)(2 * blockIdx.x) * HD * HD;
    __nv_bfloat16* lo = g_w + (size_t)(2 * blockIdx.x + 1) * HD * HD;
    int n = threadIdx.x;
    for (int k0 = 0; k0 < HD; k0 += 4) {
        float4 v;
        v.x = W[(k0 + 0) * HD + n];
        v.y = W[(k0 + 1) * HD + n];
        v.z = W[(k0 + 2) * HD + n];
        v.w = W[(k0 + 3) * HD + n];
        int off = n * HD + k0;
        __nv_bfloat16 hx = __float2bfloat16_rn(v.x), hy = __float2bfloat16_rn(v.y);
        __nv_bfloat16 hz = __float2bfloat16_rn(v.z), hw = __float2bfloat16_rn(v.w);
        uint2 ph, pl;
        ph.x = (uint32_t)__bfloat16_as_ushort(hx) | ((uint32_t)__bfloat16_as_ushort(hy) << 16);
        ph.y = (uint32_t)__bfloat16_as_ushort(hz) | ((uint32_t)__bfloat16_as_ushort(hw) << 16);
        __nv_bfloat16 gx = __float2bfloat16_rn(v.x - __bfloat162float(hx));
        __nv_bfloat16 gy = __float2bfloat16_rn(v.y - __bfloat162float(hy));
        __nv_bfloat16 gz = __float2bfloat16_rn(v.z - __bfloat162float(hz));
        __nv_bfloat16 gw = __float2bfloat16_rn(v.w - __bfloat162float(hw));
        pl.x = (uint32_t)__bfloat16_as_ushort(gx) | ((uint32_t)__bfloat16_as_ushort(gy) << 16);
        pl.y = (uint32_t)__bfloat16_as_ushort(gz) | ((uint32_t)__bfloat16_as_ushort(gw) << 16);
        *(uint2*)&hi[off] = ph;
        *(uint2*)&lo[off] = pl;
    }
}

// ---------------- aggregation: warp/node, unroll-2 (R4-proven) -------------
// CONV0: layer-1 variant also emits the bf16 hi/lo split of the node's own
// row (replaces the separate conv0 pass over x0).
template <bool CONV0>
__global__ void agg_kernel_t(const float* __restrict__ xin) {
    int warp = (blockIdx.x * blockDim.x + threadIdx.x) >> 5;
    if (warp >= NN) return;
    int lane = threadIdx.x & 31;
    int s = g_rowstart[warp];
    int e = g_rowstart[warp + 1];
    float4 acc = make_float4(0.f, 0.f, 0.f, 0.f);
    int j = s;
    for (; j + 1 < e; j += 2) {
        int u0 = g_eidx[j], u1 = g_eidx[j + 1];
        float4 v0 = *(const float4*)&xin[(size_t)u0 * HD + lane * 4];
        float4 v1 = *(const float4*)&xin[(size_t)u1 * HD + lane * 4];
        acc.x += v0.x + v1.x; acc.y += v0.y + v1.y;
        acc.z += v0.z + v1.z; acc.w += v0.w + v1.w;
    }
    if (j < e) {
        int u = g_eidx[j];
        float4 v = *(const float4*)&xin[(size_t)u * HD + lane * 4];
        acc.x += v.x; acc.y += v.y; acc.z += v.z; acc.w += v.w;
    }
    write_hilo(g_ah, g_al, warp, lane, acc);
    if (CONV0) {
        float4 own = *(const float4*)&xin[(size_t)warp * HD + lane * 4];
        write_hilo(g_xh, g_xl, warp, lane, own);
    }
}

// ---------------- HMMA GEMM (R4-proven, store epilogue only) ---------------
__global__ void __launch_bounds__(256, 2)
gemm_kernel(const __nv_bfloat16* __restrict__ xh, const __nv_bfloat16* __restrict__ xl,
            const __nv_bfloat16* __restrict__ ah, const __nv_bfloat16* __restrict__ al,
            const __nv_bfloat16* __restrict__ wrh, const __nv_bfloat16* __restrict__ wrl,
            const __nv_bfloat16* __restrict__ weh, const __nv_bfloat16* __restrict__ wel,
            const float* __restrict__ bias, float* __restrict__ yout) {
    extern __shared__ char smem[];
    __shared__ const uint4* Atab[6];
    __shared__ const uint4* Btab[6];
    const int tid = threadIdx.x, lane = tid & 31, wid = tid >> 5;
    const int wm = wid >> 1, wn = wid & 1;
    const int tile = blockIdx.x;

    if (tid == 0) {
        size_t toff = (size_t)tile * 128 * HD;
        Atab[0] = (const uint4*)(xh + toff); Atab[1] = (const uint4*)(ah + toff);
        Atab[2] = (const uint4*)(xl + toff); Atab[3] = (const uint4*)(al + toff);
        Atab[4] = Atab[0];                   Atab[5] = Atab[1];
        Btab[0] = (const uint4*)wrh; Btab[1] = (const uint4*)weh;
        Btab[2] = (const uint4*)wrh; Btab[3] = (const uint4*)weh;
        Btab[4] = (const uint4*)wrl; Btab[5] = (const uint4*)wel;
    }
    __syncthreads();
    const uint32_t sbase = smem_to_u32(smem);

    auto prefetch = [&](int cc, int st) {
        int seg = cc >> 1, ko4 = (cc & 1) << 3;
        const uint4* As = Atab[seg];
        const uint4* Bs = Btab[seg];
        uint32_t sA = sbase + st * 32768;
        uint32_t sB = sA + 16384;
        #pragma unroll
        for (int i = 0; i < 4; i++) {
            int idx = tid + 256 * i;
            int row = idx >> 3, c4 = idx & 7;
            int sw = (row * 8 + (c4 ^ (row & 7))) * 16;
            CP_ASYNC16(sA + sw, As + row * 16 + ko4 + c4);
            CP_ASYNC16(sB + sw, Bs + row * 16 + ko4 + c4);
        }
    };

    prefetch(0, 0); CP_COMMIT();
    prefetch(1, 1); CP_COMMIT();
    prefetch(2, 2); CP_COMMIT();

    float acc[2][8][4] = {};
    int st = 0;
    #pragma unroll 1
    for (int c = 0; c < 12; c++) {
        CP_WAIT2();
        __syncthreads();
        uint32_t sA = sbase + st * 32768;
        uint32_t sB = sA + 16384;
        #pragma unroll
        for (int kk = 0; kk < 4; kk++) {
            uint32_t a0[4], a1[4];
            {
                int row = wm * 32 + (lane & 15);
                int c4 = kk * 2 + (lane >> 4);
                ldsm_x4(a0, sA + (row * 8 + (c4 ^ (row & 7))) * 16);
                int row1 = row + 16;
                ldsm_x4(a1, sA + (row1 * 8 + (c4 ^ (row1 & 7))) * 16);
            }
            uint32_t b[4][4];
            #pragma unroll
            for (int p = 0; p < 4; p++) {
                int nrow = wn * 64 + p * 16 + ((lane >> 4) << 3) + (lane & 7);
                int c4 = kk * 2 + ((lane >> 3) & 1);
                ldsm_x4(b[p], sB + (nrow * 8 + (c4 ^ (nrow & 7))) * 16);
            }
            #pragma unroll
            for (int nt = 0; nt < 8; nt++) {
                mma16816(acc[0][nt], a0, &b[nt >> 1][(nt & 1) * 2]);
                mma16816(acc[1][nt], a1, &b[nt >> 1][(nt & 1) * 2]);
            }
        }
        __syncthreads();
        if (c + 3 < 12) prefetch(c + 3, st);
        CP_COMMIT();
        st = (st == 2) ? 0 : st + 1;
    }

    int r0 = tile * 128 + wm * 32 + (lane >> 2);
    int cb = wn * 64 + (lane & 3) * 2;
    #pragma unroll
    for (int mt = 0; mt < 2; mt++) {
        #pragma unroll
        for (int nt = 0; nt < 8; nt++) {
            int col = cb + nt * 8;
            int row = r0 + mt * 16;
            float bx = bias[col], by = bias[col + 1];
            float2 v;
            v.x = fmaxf(acc[mt][nt][0] + bx, 0.f);
            v.y = fmaxf(acc[mt][nt][1] + by, 0.f);
            *(float2*)&yout[(size_t)row * HD + col] = v;
            v.x = fmaxf(acc[mt][nt][2] + bx, 0.f);
            v.y = fmaxf(acc[mt][nt][3] + by, 0.f);
            *(float2*)&yout[(size_t)(row + 8) * HD + col] = v;
        }
    }
}

// ---------------- mixup: writes fp32 x + bf16 hi/lo ------------------------
__global__ void mixup_kernel(const float* __restrict__ lam, int which,
                             const float* __restrict__ yin) {
    int warp = (blockIdx.x * blockDim.x + threadIdx.x) >> 5;
    if (warp >= NN) return;
    int lane = threadIdx.x & 31;
    const int* perm = which ? g_p2 : g_p1;
    int p = perm[warp];
    float l = lam[0];
    float4 a = *(const float4*)&yin[(size_t)warp * HD + lane * 4];
    float4 b = *(const float4*)&yin[(size_t)p * HD + lane * 4];
    float4 o;
    o.x = l * a.x + (1.f - l) * b.x;
    o.y = l * a.y + (1.f - l) * b.y;
    o.z = l * a.z + (1.f - l) * b.z;
    o.w = l * a.w + (1.f - l) * b.w;
    *(float4*)&g_x[(size_t)warp * HD + lane * 4] = o;
    write_hilo(g_xh, g_xl, warp, lane, o);
}

// ---------------- pooling (mixup3 no-op under segment-sum) -----------------
__global__ void pool_kernel(const float* __restrict__ yin) {
    int g = blockIdx.x >> 2;
    int c = blockIdx.x & 3;
    int t = threadIdx.x;
    float acc = 0.f;
    int base = g * SEG + c * 100;
    #pragma unroll 4
    for (int r = 0; r < 100; r++)
        acc += yin[(size_t)(base + r) * HD + t];
    atomicAdd(&g_pooled[g * HD + t], acc);
}

// ---------------- head -----------------------------------------------------
__global__ void head_kernel(const float* __restrict__ Wl,
                            const float* __restrict__ bl,
                            float* __restrict__ out) {
    int g = blockIdx.x;
    int lane = threadIdx.x;
    float pv[4];
    #pragma unroll
    for (int q = 0; q < 4; q++) pv[q] = g_pooled[g * HD + lane + q * 32];
    float logits[OUTC];
    #pragma unroll
    for (int o = 0; o < OUTC; o++) {
        float s = 0.f;
        #pragma unroll
        for (int q = 0; q < 4; q++)
            s += pv[q] * Wl[(lane + q * 32) * OUTC + o];
        #pragma unroll
        for (int off = 16; off; off >>= 1)
            s += __shfl_down_sync(0xffffffffu, s, off);
        logits[o] = s;
    }
    if (lane == 0) {
        float m = -1e30f;
        #pragma unroll
        for (int o = 0; o < OUTC; o++) {
            logits[o] += bl[o];
            m = fmaxf(m, logits[o]);
        }
        float se = 0.f;
        #pragma unroll
        for (int o = 0; o < OUTC; o++) se += expf(logits[o] - m);
        float lse = m + logf(se);
        #pragma unroll
        for (int o = 0; o < OUTC; o++) out[g * OUTC + o] = logits[o] - lse;
    }
}

// ---------------- launch ----------------------------------------------------
extern "C" void kernel_launch(void* const* d_in, const int* in_sizes, int n_in,
                              void* d_out, int out_size) {
    const float* x0      = (const float*)d_in[0];
    const void*  eidx    = d_in[1];
    const float* lam     = (const float*)d_in[2];
    const void*  perm1   = d_in[5];
    const void*  perm2   = d_in[6];
    const float* W1_rel  = (const float*)d_in[8];
    const float* b1_rel  = (const float*)d_in[9];
    const float* W1_root = (const float*)d_in[10];
    const float* W2_rel  = (const float*)d_in[11];
    const float* b2_rel  = (const float*)d_in[12];
    const float* W2_root = (const float*)d_in[13];
    const float* W_lin   = (const float*)d_in[14];
    const float* b_lin   = (const float*)d_in[15];
    float* out = (float*)d_out;

    const int GEMM_SMEM = 3 * 32768;
    static int smem_set = 0;
    if (!smem_set) {
        cudaFuncSetAttribute(gemm_kernel,
                             cudaFuncAttributeMaxDynamicSharedMemorySize, GEMM_SMEM);
        smem_set = 1;
    }

    init_kernel<<<(NN + 255) / 256, 256>>>((const unsigned*)eidx);
    convhist_kernel<<<(NE + 255) / 256, 256>>>(eidx, perm1, perm2);
    scan1_kernel<<<(NN + 255) / 256, 256>>>();
    scan2_kernel<<<1, 256>>>();
    scan3_kernel<<<(NN + 255) / 256, 256>>>();
    scatter_kernel<<<(NE + 255) / 256, 256>>>();

    wprep_kernel<<<4, 128>>>(W1_root, W1_rel, W2_root, W2_rel);

    __nv_bfloat16 *xh, *xl, *ah, *al, *w;
    float *gx, *gy;
    cudaGetSymbolAddress((void**)&xh, g_xh);
    cudaGetSymbolAddress((void**)&xl, g_xl);
    cudaGetSymbolAddress((void**)&ah, g_ah);
    cudaGetSymbolAddress((void**)&al, g_al);
    cudaGetSymbolAddress((void**)&w,  g_w);
    cudaGetSymbolAddress((void**)&gx, g_x);
    cudaGetSymbolAddress((void**)&gy, g_y);
    __nv_bfloat16* w0rh = w + 0 * HD * HD;  __nv_bfloat16* w0rl = w + 1 * HD * HD;
    __nv_bfloat16* w0eh = w + 2 * HD * HD;  __nv_bfloat16* w0el = w + 3 * HD * HD;
    __nv_bfloat16* w1rh = w + 4 * HD * HD;  __nv_bfloat16* w1rl = w + 5 * HD * HD;
    __nv_bfloat16* w1eh = w + 6 * HD * HD;  __nv_bfloat16* w1el = w + 7 * HD * HD;

    // Layer 1 (agg also emits x0's bf16 split: conv0 fused)
    agg_kernel_t<true><<<(NN * 32 + 255) / 256, 256>>>(x0);
    gemm_kernel<<<NT, 256, GEMM_SMEM>>>(xh, xl, ah, al,
                                        w0rh, w0rl, w0eh, w0el, b1_rel, gy);
    mixup_kernel<<<(NN * 32 + 255) / 256, 256>>>(lam, 0, gy);

    // Layer 2
    agg_kernel_t<false><<<(NN * 32 + 255) / 256, 256>>>(gx);
    gemm_kernel<<<NT, 256, GEMM_SMEM>>>(xh, xl, ah, al,
                                        w1rh, w1rl, w1eh, w1el, b2_rel, gy);
    mixup_kernel<<<(NN * 32 + 255) / 256, 256>>>(lam, 1, gy);

    // Layer 3 (conv2 weights reused; mixup3 invariant under pooling)
    agg_kernel_t<false><<<(NN * 32 + 255) / 256, 256>>>(gx);
    gemm_kernel<<<NT, 256, GEMM_SMEM>>>(xh, xl, ah, al,
                                        w1rh, w1rl, w1eh, w1el, b2_rel, gy);

    pool_kernel<<<NG * 4, 128>>>(gy);
    head_kernel<<<NG, 32>>>(W_lin, b_lin, out);
}

// round 10
// speedup vs baseline: 2.2844x; 1.0226x over previous
#include <cuda_runtime.h>
#include <cuda_bf16.h>
#include <cuda_fp16.h>
#include <math.h>
#include <stdint.h>

#define NN 51200      // nodes
#define NE 819200     // edges
#define HD 128        // hidden / in dim
#define NG 128        // graphs
#define SEG 400       // nodes per graph
#define OUTC 10
#define NT  (NN / 128)          // 400 M-tiles

// ---------------- scratch (device globals) ---------------------------------
__device__ float g_y[NN * HD];     // conv output (post-relu)
__device__ __align__(16) __half        g_xf[NN * HD];   // fp16 gather image of x
__device__ __align__(16) __nv_bfloat16 g_xh[NN * HD];   // bf16 hi of x
__device__ __align__(16) __nv_bfloat16 g_xl[NN * HD];   // bf16 lo of x
__device__ __align__(16) __nv_bfloat16 g_ah[NN * HD];   // bf16 hi of agg
__device__ __align__(16) __nv_bfloat16 g_al[NN * HD];   // bf16 lo of agg
__device__ __align__(16) __nv_bfloat16 g_w[8 * HD * HD];
__device__ int   g_src[NE];
__device__ int   g_dst[NE];
__device__ int   g_p1[NN];
__device__ int   g_p2[NN];
__device__ int   g_cnt[NN];
__device__ int   g_scanL[NN];
__device__ int   g_bsum[256];
__device__ int   g_boff[256];
__device__ int   g_rowstart[NN + 1];
__device__ int   g_cursor[NN];
__device__ int   g_eidx[NE];
__device__ float g_pooled[NG * HD];
__device__ int   g_is64;

// ---------------- helpers ---------------------------------------------------
__device__ __forceinline__ uint32_t smem_to_u32(const void* p) {
    uint32_t a;
    asm("{ .reg .u64 t; cvta.to.shared.u64 t, %1; cvt.u32.u64 %0, t; }"
        : "=r"(a) : "l"(p));
    return a;
}
#define CP_ASYNC16(dst, src) \
    asm volatile("cp.async.cg.shared.global [%0], [%1], 16;" \
                 :: "r"(dst), "l"(src) : "memory")
#define CP_COMMIT() asm volatile("cp.async.commit_group;" ::: "memory")
#define CP_WAIT2()  asm volatile("cp.async.wait_group 2;" ::: "memory")

__device__ __forceinline__ void ldsm_x4(uint32_t* r, uint32_t addr) {
    asm volatile("ldmatrix.sync.aligned.m8n8.x4.shared.b16 {%0,%1,%2,%3}, [%4];"
                 : "=r"(r[0]), "=r"(r[1]), "=r"(r[2]), "=r"(r[3]) : "r"(addr));
}
__device__ __forceinline__ void mma16816(float* c, const uint32_t* a, const uint32_t* b) {
    asm volatile("mma.sync.aligned.m16n8k16.row.col.f32.bf16.bf16.f32 "
                 "{%0,%1,%2,%3},{%4,%5,%6,%7},{%8,%9},{%0,%1,%2,%3};"
                 : "+f"(c[0]), "+f"(c[1]), "+f"(c[2]), "+f"(c[3])
                 : "r"(a[0]), "r"(a[1]), "r"(a[2]), "r"(a[3]), "r"(b[0]), "r"(b[1]));
}

__device__ __forceinline__ void write_hilo(__nv_bfloat16* hi, __nv_bfloat16* lo,
                                           int node, int lane, float4 v) {
    int off = node * HD + lane * 4;
    __nv_bfloat16 hx = __float2bfloat16_rn(v.x), hy = __float2bfloat16_rn(v.y);
    __nv_bfloat16 hz = __float2bfloat16_rn(v.z), hw = __float2bfloat16_rn(v.w);
    uint2 ph, pl;
    ph.x = (uint32_t)__bfloat16_as_ushort(hx) | ((uint32_t)__bfloat16_as_ushort(hy) << 16);
    ph.y = (uint32_t)__bfloat16_as_ushort(hz) | ((uint32_t)__bfloat16_as_ushort(hw) << 16);
    __nv_bfloat16 gx = __float2bfloat16_rn(v.x - __bfloat162float(hx));
    __nv_bfloat16 gy = __float2bfloat16_rn(v.y - __bfloat162float(hy));
    __nv_bfloat16 gz = __float2bfloat16_rn(v.z - __bfloat162float(hz));
    __nv_bfloat16 gw = __float2bfloat16_rn(v.w - __bfloat162float(hw));
    pl.x = (uint32_t)__bfloat16_as_ushort(gx) | ((uint32_t)__bfloat16_as_ushort(gy) << 16);
    pl.y = (uint32_t)__bfloat16_as_ushort(gz) | ((uint32_t)__bfloat16_as_ushort(gw) << 16);
    *(uint2*)&hi[off] = ph;
    *(uint2*)&lo[off] = pl;
}

__device__ __forceinline__ void write_f16(__half* xf, int node, int lane, float4 v) {
    __half2 h0 = __floats2half2_rn(v.x, v.y);
    __half2 h1 = __floats2half2_rn(v.z, v.w);
    uint2 p;
    p.x = *(const uint32_t*)&h0;
    p.y = *(const uint32_t*)&h1;
    *(uint2*)&xf[node * HD + lane * 4] = p;
}

// ---------------- init: zero counters/pooled + dtype detect ----------------
__global__ void init_kernel(const unsigned* __restrict__ e) {
    int i = blockIdx.x * blockDim.x + threadIdx.x;
    if (i < NN) g_cnt[i] = 0;
    if (i < NG * HD) g_pooled[i] = 0.0f;
    if (i == 0) {
        int all0 = 1;
        #pragma unroll 1
        for (int k = 0; k < 128; k++)
            if (e[2 * k + 1] != 0u) { all0 = 0; break; }
        g_is64 = all0;
    }
}

// fused convert + histogram
__global__ void convhist_kernel(const void* __restrict__ eraw,
                                const void* __restrict__ p1raw,
                                const void* __restrict__ p2raw) {
    int i = blockIdx.x * blockDim.x + threadIdx.x;
    const bool is64 = (g_is64 != 0);
    if (i < NE) {
        int s = is64 ? (int)((const long long*)eraw)[i] : ((const int*)eraw)[i];
        int d = is64 ? (int)((const long long*)eraw)[NE + i] : ((const int*)eraw)[NE + i];
        g_src[i] = s;
        g_dst[i] = d;
        atomicAdd(&g_cnt[d], 1);
    }
    if (i < NN) {
        g_p1[i] = is64 ? (int)((const long long*)p1raw)[i] : ((const int*)p1raw)[i];
        g_p2[i] = is64 ? (int)((const long long*)p2raw)[i] : ((const int*)p2raw)[i];
    }
}

// ---------------- 3-kernel scan chain (R4-proven) ---------------------------
__global__ void scan1_kernel() {
    __shared__ int sh[256];
    int b = blockIdx.x, t = threadIdx.x;
    int i = b * 256 + t;
    int v = (i < NN) ? g_cnt[i] : 0;
    sh[t] = v;
    __syncthreads();
    #pragma unroll
    for (int off = 1; off < 256; off <<= 1) {
        int add = (t >= off) ? sh[t - off] : 0;
        __syncthreads();
        sh[t] += add;
        __syncthreads();
    }
    if (i < NN) g_scanL[i] = sh[t] - v;
    if (t == 255) g_bsum[b] = sh[255];
}

__global__ void scan2_kernel() {
    __shared__ int sh[256];
    int t = threadIdx.x;
    int v = (t < (NN + 255) / 256) ? g_bsum[t] : 0;
    sh[t] = v;
    __syncthreads();
    #pragma unroll
    for (int off = 1; off < 256; off <<= 1) {
        int add = (t >= off) ? sh[t - off] : 0;
        __syncthreads();
        sh[t] += add;
        __syncthreads();
    }
    g_boff[t] = sh[t] - v;
}

__global__ void scan3_kernel() {
    int i = blockIdx.x * blockDim.x + threadIdx.x;
    if (i < NN) {
        int rs = g_scanL[i] + g_boff[i >> 8];
        g_rowstart[i] = rs;
        g_cursor[i] = rs;
    }
    if (i == 0) g_rowstart[NN] = NE;
}

__global__ void scatter_kernel() {
    int e = blockIdx.x * blockDim.x + threadIdx.x;
    if (e < NE) {
        int pos = atomicAdd(&g_cursor[g_dst[e]], 1);
        g_eidx[pos] = g_src[e];
    }
}

// ---------------- weight prep: transpose + bf16 split ----------------------
__global__ void wprep_kernel(const float* __restrict__ W0r,
                             const float* __restrict__ W0e,
                             const float* __restrict__ W1r,
                             const float* __restrict__ W1e) {
    const float* Ws[4] = {W0r, W0e, W1r, W1e};
    const float* W = Ws[blockIdx.x];
    __nv_bfloat16* hi = g_w + (size_t)(2 * blockIdx.x) * HD * HD;
    __nv_bfloat16* lo = g_w + (size_t)(2 * blockIdx.x + 1) * HD * HD;
    int n = threadIdx.x;
    for (int k0 = 0; k0 < HD; k0 += 4) {
        float4 v;
        v.x = W[(k0 + 0) * HD + n];
        v.y = W[(k0 + 1) * HD + n];
        v.z = W[(k0 + 2) * HD + n];
        v.w = W[(k0 + 3) * HD + n];
        int off = n * HD + k0;
        __nv_bfloat16 hx = __float2bfloat16_rn(v.x), hy = __float2bfloat16_rn(v.y);
        __nv_bfloat16 hz = __float2bfloat16_rn(v.z), hw = __float2bfloat16_rn(v.w);
        uint2 ph, pl;
        ph.x = (uint32_t)__bfloat16_as_ushort(hx) | ((uint32_t)__bfloat16_as_ushort(hy) << 16);
        ph.y = (uint32_t)__bfloat16_as_ushort(hz) | ((uint32_t)__bfloat16_as_ushort(hw) << 16);
        __nv_bfloat16 gx = __float2bfloat16_rn(v.x - __bfloat162float(hx));
        __nv_bfloat16 gy = __float2bfloat16_rn(v.y - __bfloat162float(hy));
        __nv_bfloat16 gz = __float2bfloat16_rn(v.z - __bfloat162float(hz));
        __nv_bfloat16 gw = __float2bfloat16_rn(v.w - __bfloat162float(hw));
        pl.x = (uint32_t)__bfloat16_as_ushort(gx) | ((uint32_t)__bfloat16_as_ushort(gy) << 16);
        pl.y = (uint32_t)__bfloat16_as_ushort(gz) | ((uint32_t)__bfloat16_as_ushort(gw) << 16);
        *(uint2*)&hi[off] = ph;
        *(uint2*)&lo[off] = pl;
    }
}

// ---------------- x0 prep: bf16 hi/lo + fp16 gather image -------------------
__global__ void xf0_kernel(const float* __restrict__ xin) {
    int warp = (blockIdx.x * blockDim.x + threadIdx.x) >> 5;
    if (warp >= NN) return;
    int lane = threadIdx.x & 31;
    float4 v = *(const float4*)&xin[(size_t)warp * HD + lane * 4];
    write_hilo(g_xh, g_xl, warp, lane, v);
    write_f16(g_xf, warp, lane, v);
}

// ---------------- aggregation: warp/node, unroll-2, fp16 gather ------------
__global__ void agg_kernel() {
    int warp = (blockIdx.x * blockDim.x + threadIdx.x) >> 5;
    if (warp >= NN) return;
    int lane = threadIdx.x & 31;
    int s = g_rowstart[warp];
    int e = g_rowstart[warp + 1];
    float4 acc = make_float4(0.f, 0.f, 0.f, 0.f);
    int j = s;
    for (; j + 1 < e; j += 2) {
        int u0 = g_eidx[j], u1 = g_eidx[j + 1];
        uint2 p0 = *(const uint2*)&g_xf[u0 * HD + lane * 4];
        uint2 p1 = *(const uint2*)&g_xf[u1 * HD + lane * 4];
        float2 a0 = __half22float2(*(const __half2*)&p0.x);
        float2 b0 = __half22float2(*(const __half2*)&p0.y);
        float2 a1 = __half22float2(*(const __half2*)&p1.x);
        float2 b1 = __half22float2(*(const __half2*)&p1.y);
        acc.x += a0.x + a1.x; acc.y += a0.y + a1.y;
        acc.z += b0.x + b1.x; acc.w += b0.y + b1.y;
    }
    if (j < e) {
        int u = g_eidx[j];
        uint2 p = *(const uint2*)&g_xf[u * HD + lane * 4];
        float2 a = __half22float2(*(const __half2*)&p.x);
        float2 b = __half22float2(*(const __half2*)&p.y);
        acc.x += a.x; acc.y += a.y; acc.z += b.x; acc.w += b.y;
    }
    write_hilo(g_ah, g_al, warp, lane, acc);
}

// ---------------- HMMA GEMM (R4-proven, store epilogue only) ---------------
__global__ void __launch_bounds__(256, 2)
gemm_kernel(const __nv_bfloat16* __restrict__ xh, const __nv_bfloat16* __restrict__ xl,
            const __nv_bfloat16* __restrict__ ah, const __nv_bfloat16* __restrict__ al,
            const __nv_bfloat16* __restrict__ wrh, const __nv_bfloat16* __restrict__ wrl,
            const __nv_bfloat16* __restrict__ weh, const __nv_bfloat16* __restrict__ wel,
            const float* __restrict__ bias, float* __restrict__ yout) {
    extern __shared__ char smem[];
    __shared__ const uint4* Atab[6];
    __shared__ const uint4* Btab[6];
    const int tid = threadIdx.x, lane = tid & 31, wid = tid >> 5;
    const int wm = wid >> 1, wn = wid & 1;
    const int tile = blockIdx.x;

    if (tid == 0) {
        size_t toff = (size_t)tile * 128 * HD;
        Atab[0] = (const uint4*)(xh + toff); Atab[1] = (const uint4*)(ah + toff);
        Atab[2] = (const uint4*)(xl + toff); Atab[3] = (const uint4*)(al + toff);
        Atab[4] = Atab[0];                   Atab[5] = Atab[1];
        Btab[0] = (const uint4*)wrh; Btab[1] = (const uint4*)weh;
        Btab[2] = (const uint4*)wrh; Btab[3] = (const uint4*)weh;
        Btab[4] = (const uint4*)wrl; Btab[5] = (const uint4*)wel;
    }
    __syncthreads();
    const uint32_t sbase = smem_to_u32(smem);

    auto prefetch = [&](int cc, int st) {
        int seg = cc >> 1, ko4 = (cc & 1) << 3;
        const uint4* As = Atab[seg];
        const uint4* Bs = Btab[seg];
        uint32_t sA = sbase + st * 32768;
        uint32_t sB = sA + 16384;
        #pragma unroll
        for (int i = 0; i < 4; i++) {
            int idx = tid + 256 * i;
            int row = idx >> 3, c4 = idx & 7;
            int sw = (row * 8 + (c4 ^ (row & 7))) * 16;
            CP_ASYNC16(sA + sw, As + row * 16 + ko4 + c4);
            CP_ASYNC16(sB + sw, Bs + row * 16 + ko4 + c4);
        }
    };

    prefetch(0, 0); CP_COMMIT();
    prefetch(1, 1); CP_COMMIT();
    prefetch(2, 2); CP_COMMIT();

    float acc[2][8][4] = {};
    int st = 0;
    #pragma unroll 1
    for (int c = 0; c < 12; c++) {
        CP_WAIT2();
        __syncthreads();
        uint32_t sA = sbase + st * 32768;
        uint32_t sB = sA + 16384;
        #pragma unroll
        for (int kk = 0; kk < 4; kk++) {
            uint32_t a0[4], a1[4];
            {
                int row = wm * 32 + (lane & 15);
                int c4 = kk * 2 + (lane >> 4);
                ldsm_x4(a0, sA + (row * 8 + (c4 ^ (row & 7))) * 16);
                int row1 = row + 16;
                ldsm_x4(a1, sA + (row1 * 8 + (c4 ^ (row1 & 7))) * 16);
            }
            uint32_t b[4][4];
            #pragma unroll
            for (int p = 0; p < 4; p++) {
                int nrow = wn * 64 + p * 16 + ((lane >> 4) << 3) + (lane & 7);
                int c4 = kk * 2 + ((lane >> 3) & 1);
                ldsm_x4(b[p], sB + (nrow * 8 + (c4 ^ (nrow & 7))) * 16);
            }
            #pragma unroll
            for (int nt = 0; nt < 8; nt++) {
                mma16816(acc[0][nt], a0, &b[nt >> 1][(nt & 1) * 2]);
                mma16816(acc[1][nt], a1, &b[nt >> 1][(nt & 1) * 2]);
            }
        }
        __syncthreads();
        if (c + 3 < 12) prefetch(c + 3, st);
        CP_COMMIT();
        st = (st == 2) ? 0 : st + 1;
    }

    int r0 = tile * 128 + wm * 32 + (lane >> 2);
    int cb = wn * 64 + (lane & 3) * 2;
    #pragma unroll
    for (int mt = 0; mt < 2; mt++) {
        #pragma unroll
        for (int nt = 0; nt < 8; nt++) {
            int col = cb + nt * 8;
            int row = r0 + mt * 16;
            float bx = bias[col], by = bias[col + 1];
            float2 v;
            v.x = fmaxf(acc[mt][nt][0] + bx, 0.f);
            v.y = fmaxf(acc[mt][nt][1] + by, 0.f);
            *(float2*)&yout[(size_t)row * HD + col] = v;
            v.x = fmaxf(acc[mt][nt][2] + bx, 0.f);
            v.y = fmaxf(acc[mt][nt][3] + by, 0.f);
            *(float2*)&yout[(size_t)(row + 8) * HD + col] = v;
        }
    }
}

// ---------------- mixup: writes bf16 hi/lo + fp16 gather image -------------
__global__ void mixup_kernel(const float* __restrict__ lam, int which,
                             const float* __restrict__ yin) {
    int warp = (blockIdx.x * blockDim.x + threadIdx.x) >> 5;
    if (warp >= NN) return;
    int lane = threadIdx.x & 31;
    const int* perm = which ? g_p2 : g_p1;
    int p = perm[warp];
    float l = lam[0];
    float4 a = *(const float4*)&yin[(size_t)warp * HD + lane * 4];
    float4 b = *(const float4*)&yin[(size_t)p * HD + lane * 4];
    float4 o;
    o.x = l * a.x + (1.f - l) * b.x;
    o.y = l * a.y + (1.f - l) * b.y;
    o.z = l * a.z + (1.f - l) * b.z;
    o.w = l * a.w + (1.f - l) * b.w;
    write_hilo(g_xh, g_xl, warp, lane, o);
    write_f16(g_xf, warp, lane, o);
}

// ---------------- pooling (mixup3 no-op under segment-sum) -----------------
__global__ void pool_kernel(const float* __restrict__ yin) {
    int g = blockIdx.x >> 2;
    int c = blockIdx.x & 3;
    int t = threadIdx.x;
    float acc = 0.f;
    int base = g * SEG + c * 100;
    #pragma unroll 4
    for (int r = 0; r < 100; r++)
        acc += yin[(size_t)(base + r) * HD + t];
    atomicAdd(&g_pooled[g * HD + t], acc);
}

// ---------------- head -----------------------------------------------------
__global__ void head_kernel(const float* __restrict__ Wl,
                            const float* __restrict__ bl,
                            float* __restrict__ out) {
    int g = blockIdx.x;
    int lane = threadIdx.x;
    float pv[4];
    #pragma unroll
    for (int q = 0; q < 4; q++) pv[q] = g_pooled[g * HD + lane + q * 32];
    float logits[OUTC];
    #pragma unroll
    for (int o = 0; o < OUTC; o++) {
        float s = 0.f;
        #pragma unroll
        for (int q = 0; q < 4; q++)
            s += pv[q] * Wl[(lane + q * 32) * OUTC + o];
        #pragma unroll
        for (int off = 16; off; off >>= 1)
            s += __shfl_down_sync(0xffffffffu, s, off);
        logits[o] = s;
    }
    if (lane == 0) {
        float m = -1e30f;
        #pragma unroll
        for (int o = 0; o < OUTC; o++) {
            logits[o] += bl[o];
            m = fmaxf(m, logits[o]);
        }
        float se = 0.f;
        #pragma unroll
        for (int o = 0; o < OUTC; o++) se += expf(logits[o] - m);
        float lse = m + logf(se);
        #pragma unroll
        for (int o = 0; o < OUTC; o++) out[g * OUTC + o] = logits[o] - lse;
    }
}

// ---------------- launch ----------------------------------------------------
extern "C" void kernel_launch(void* const* d_in, const int* in_sizes, int n_in,
                              void* d_out, int out_size) {
    const float* x0      = (const float*)d_in[0];
    const void*  eidx    = d_in[1];
    const float* lam     = (const float*)d_in[2];
    const void*  perm1   = d_in[5];
    const void*  perm2   = d_in[6];
    const float* W1_rel  = (const float*)d_in[8];
    const float* b1_rel  = (const float*)d_in[9];
    const float* W1_root = (const float*)d_in[10];
    const float* W2_rel  = (const float*)d_in[11];
    const float* b2_rel  = (const float*)d_in[12];
    const float* W2_root = (const float*)d_in[13];
    const float* W_lin   = (const float*)d_in[14];
    const float* b_lin   = (const float*)d_in[15];
    float* out = (float*)d_out;

    const int GEMM_SMEM = 3 * 32768;
    static int smem_set = 0;
    if (!smem_set) {
        cudaFuncSetAttribute(gemm_kernel,
                             cudaFuncAttributeMaxDynamicSharedMemorySize, GEMM_SMEM);
        smem_set = 1;
    }

    init_kernel<<<(NN + 255) / 256, 256>>>((const unsigned*)eidx);
    convhist_kernel<<<(NE + 255) / 256, 256>>>(eidx, perm1, perm2);
    scan1_kernel<<<(NN + 255) / 256, 256>>>();
    scan2_kernel<<<1, 256>>>();
    scan3_kernel<<<(NN + 255) / 256, 256>>>();
    scatter_kernel<<<(NE + 255) / 256, 256>>>();

    wprep_kernel<<<4, 128>>>(W1_root, W1_rel, W2_root, W2_rel);
    xf0_kernel<<<(NN * 32 + 255) / 256, 256>>>(x0);

    __nv_bfloat16 *xh, *xl, *ah, *al, *w;
    float *gy;
    cudaGetSymbolAddress((void**)&xh, g_xh);
    cudaGetSymbolAddress((void**)&xl, g_xl);
    cudaGetSymbolAddress((void**)&ah, g_ah);
    cudaGetSymbolAddress((void**)&al, g_al);
    cudaGetSymbolAddress((void**)&w,  g_w);
    cudaGetSymbolAddress((void**)&gy, g_y);
    __nv_bfloat16* w0rh = w + 0 * HD * HD;  __nv_bfloat16* w0rl = w + 1 * HD * HD;
    __nv_bfloat16* w0eh = w + 2 * HD * HD;  __nv_bfloat16* w0el = w + 3 * HD * HD;
    __nv_bfloat16* w1rh = w + 4 * HD * HD;  __nv_bfloat16* w1rl = w + 5 * HD * HD;
    __nv_bfloat16* w1eh = w + 6 * HD * HD;  __nv_bfloat16* w1el = w + 7 * HD * HD;

    // Layer 1
    agg_kernel<<<(NN * 32 + 255) / 256, 256>>>();
    gemm_kernel<<<NT, 256, GEMM_SMEM>>>(xh, xl, ah, al,
                                        w0rh, w0rl, w0eh, w0el, b1_rel, gy);
    mixup_kernel<<<(NN * 32 + 255) / 256, 256>>>(lam, 0, gy);

    // Layer 2
    agg_kernel<<<(NN * 32 + 255) / 256, 256>>>();
    gemm_kernel<<<NT, 256, GEMM_SMEM>>>(xh, xl, ah, al,
                                        w1rh, w1rl, w1eh, w1el, b2_rel, gy);
    mixup_kernel<<<(NN * 32 + 255) / 256, 256>>>(lam, 1, gy);

    // Layer 3 (conv2 weights reused; mixup3 invariant under pooling)
    agg_kernel<<<(NN * 32 + 255) / 256, 256>>>();
    gemm_kernel<<<NT, 256, GEMM_SMEM>>>(xh, xl, ah, al,
                                        w1rh, w1rl, w1eh, w1el, b2_rel, gy);

    pool_kernel<<<NG * 4, 128>>>(gy);
    head_kernel<<<NG, 32>>>(W_lin, b_lin, out);
}

// round 11
// speedup vs baseline: 2.6351x; 1.1536x over previous
#include <cuda_runtime.h>
#include <cuda_fp16.h>
#include <math.h>
#include <stdint.h>

#define NN 51200      // nodes
#define NE 819200     // edges
#define HD 128        // hidden / in dim
#define NG 128        // graphs
#define SEG 400       // nodes per graph
#define OUTC 10
#define NT  (NN / 128)          // 400 M-tiles

// ---------------- scratch (device globals) ---------------------------------
__device__ float g_y[NN * HD];     // conv output (post-relu)
__device__ __align__(16) __half g_xh[NN * HD];   // fp16 hi of x (also gather src)
__device__ __align__(16) __half g_xl[NN * HD];   // fp16 residual of x
__device__ __align__(16) __half g_ah[NN * HD];   // fp16 hi of agg
__device__ __align__(16) __half g_al[NN * HD];   // fp16 residual of agg
__device__ __align__(16) __half g_w[4 * HD * HD]; // weight hi images [n][k]
__device__ int   g_src[NE];
__device__ int   g_dst[NE];
__device__ int   g_p1[NN];
__device__ int   g_p2[NN];
__device__ int   g_cnt[NN];
__device__ int   g_scanL[NN];
__device__ int   g_bsum[256];
__device__ int   g_boff[256];
__device__ int   g_rowstart[NN + 1];
__device__ int   g_cursor[NN];
__device__ int   g_eidx[NE];
__device__ float g_pooled[NG * HD];
__device__ int   g_is64;

// ---------------- helpers ---------------------------------------------------
__device__ __forceinline__ uint32_t smem_to_u32(const void* p) {
    uint32_t a;
    asm("{ .reg .u64 t; cvta.to.shared.u64 t, %1; cvt.u32.u64 %0, t; }"
        : "=r"(a) : "l"(p));
    return a;
}
#define CP_ASYNC16(dst, src) \
    asm volatile("cp.async.cg.shared.global [%0], [%1], 16;" \
                 :: "r"(dst), "l"(src) : "memory")
#define CP_COMMIT() asm volatile("cp.async.commit_group;" ::: "memory")
#define CP_WAIT2()  asm volatile("cp.async.wait_group 2;" ::: "memory")

__device__ __forceinline__ void ldsm_x4(uint32_t* r, uint32_t addr) {
    asm volatile("ldmatrix.sync.aligned.m8n8.x4.shared.b16 {%0,%1,%2,%3}, [%4];"
                 : "=r"(r[0]), "=r"(r[1]), "=r"(r[2]), "=r"(r[3]) : "r"(addr));
}
__device__ __forceinline__ void mma16816(float* c, const uint32_t* a, const uint32_t* b) {
    asm volatile("mma.sync.aligned.m16n8k16.row.col.f32.f16.f16.f32 "
                 "{%0,%1,%2,%3},{%4,%5,%6,%7},{%8,%9},{%0,%1,%2,%3};"
                 : "+f"(c[0]), "+f"(c[1]), "+f"(c[2]), "+f"(c[3])
                 : "r"(a[0]), "r"(a[1]), "r"(a[2]), "r"(a[3]), "r"(b[0]), "r"(b[1]));
}

__device__ __forceinline__ uint32_t pack2(__half a, __half b) {
    return (uint32_t)__half_as_ushort(a) | ((uint32_t)__half_as_ushort(b) << 16);
}

// fp16 hi/residual split: hi + lo == v to ~2^-22 relative
__device__ __forceinline__ void write_hilo(__half* hi, __half* lo,
                                           int node, int lane, float4 v) {
    int off = node * HD + lane * 4;
    __half hx = __float2half_rn(v.x), hy = __float2half_rn(v.y);
    __half hz = __float2half_rn(v.z), hw = __float2half_rn(v.w);
    uint2 ph, pl;
    ph.x = pack2(hx, hy);
    ph.y = pack2(hz, hw);
    pl.x = pack2(__float2half_rn(v.x - __half2float(hx)),
                 __float2half_rn(v.y - __half2float(hy)));
    pl.y = pack2(__float2half_rn(v.z - __half2float(hz)),
                 __float2half_rn(v.w - __half2float(hw)));
    *(uint2*)&hi[off] = ph;
    *(uint2*)&lo[off] = pl;
}

// ---------------- init: zero counters/pooled + dtype detect ----------------
__global__ void init_kernel(const unsigned* __restrict__ e) {
    int i = blockIdx.x * blockDim.x + threadIdx.x;
    if (i < NN) g_cnt[i] = 0;
    if (i < NG * HD) g_pooled[i] = 0.0f;
    if (i == 0) {
        int all0 = 1;
        #pragma unroll 1
        for (int k = 0; k < 128; k++)
            if (e[2 * k + 1] != 0u) { all0 = 0; break; }
        g_is64 = all0;
    }
}

// fused convert + histogram
__global__ void convhist_kernel(const void* __restrict__ eraw,
                                const void* __restrict__ p1raw,
                                const void* __restrict__ p2raw) {
    int i = blockIdx.x * blockDim.x + threadIdx.x;
    const bool is64 = (g_is64 != 0);
    if (i < NE) {
        int s = is64 ? (int)((const long long*)eraw)[i] : ((const int*)eraw)[i];
        int d = is64 ? (int)((const long long*)eraw)[NE + i] : ((const int*)eraw)[NE + i];
        g_src[i] = s;
        g_dst[i] = d;
        atomicAdd(&g_cnt[d], 1);
    }
    if (i < NN) {
        g_p1[i] = is64 ? (int)((const long long*)p1raw)[i] : ((const int*)p1raw)[i];
        g_p2[i] = is64 ? (int)((const long long*)p2raw)[i] : ((const int*)p2raw)[i];
    }
}

// ---------------- 3-kernel scan chain (R4-proven) ---------------------------
__global__ void scan1_kernel() {
    __shared__ int sh[256];
    int b = blockIdx.x, t = threadIdx.x;
    int i = b * 256 + t;
    int v = (i < NN) ? g_cnt[i] : 0;
    sh[t] = v;
    __syncthreads();
    #pragma unroll
    for (int off = 1; off < 256; off <<= 1) {
        int add = (t >= off) ? sh[t - off] : 0;
        __syncthreads();
        sh[t] += add;
        __syncthreads();
    }
    if (i < NN) g_scanL[i] = sh[t] - v;
    if (t == 255) g_bsum[b] = sh[255];
}

__global__ void scan2_kernel() {
    __shared__ int sh[256];
    int t = threadIdx.x;
    int v = (t < (NN + 255) / 256) ? g_bsum[t] : 0;
    sh[t] = v;
    __syncthreads();
    #pragma unroll
    for (int off = 1; off < 256; off <<= 1) {
        int add = (t >= off) ? sh[t - off] : 0;
        __syncthreads();
        sh[t] += add;
        __syncthreads();
    }
    g_boff[t] = sh[t] - v;
}

__global__ void scan3_kernel() {
    int i = blockIdx.x * blockDim.x + threadIdx.x;
    if (i < NN) {
        int rs = g_scanL[i] + g_boff[i >> 8];
        g_rowstart[i] = rs;
        g_cursor[i] = rs;
    }
    if (i == 0) g_rowstart[NN] = NE;
}

__global__ void scatter_kernel() {
    int e = blockIdx.x * blockDim.x + threadIdx.x;
    if (e < NE) {
        int pos = atomicAdd(&g_cursor[g_dst[e]], 1);
        g_eidx[pos] = g_src[e];
    }
}

// ---------------- weight prep: transpose + fp16 hi image -------------------
__global__ void wprep_kernel(const float* __restrict__ W0r,
                             const float* __restrict__ W0e,
                             const float* __restrict__ W1r,
                             const float* __restrict__ W1e) {
    const float* Ws[4] = {W0r, W0e, W1r, W1e};
    const float* W = Ws[blockIdx.x];
    __half* hi = g_w + (size_t)blockIdx.x * HD * HD;
    int n = threadIdx.x;
    for (int k0 = 0; k0 < HD; k0 += 4) {
        uint2 p;
        p.x = pack2(__float2half_rn(W[(k0 + 0) * HD + n]),
                    __float2half_rn(W[(k0 + 1) * HD + n]));
        p.y = pack2(__float2half_rn(W[(k0 + 2) * HD + n]),
                    __float2half_rn(W[(k0 + 3) * HD + n]));
        *(uint2*)&hi[n * HD + k0] = p;
    }
}

// ---------------- x0 prep: fp16 hi/lo split --------------------------------
__global__ void xprep_kernel(const float* __restrict__ xin) {
    int warp = (blockIdx.x * blockDim.x + threadIdx.x) >> 5;
    if (warp >= NN) return;
    int lane = threadIdx.x & 31;
    float4 v = *(const float4*)&xin[(size_t)warp * HD + lane * 4];
    write_hilo(g_xh, g_xl, warp, lane, v);
}

// ---------------- aggregation: warp/node, unroll-2, fp16 gather ------------
__global__ void agg_kernel() {
    int warp = (blockIdx.x * blockDim.x + threadIdx.x) >> 5;
    if (warp >= NN) return;
    int lane = threadIdx.x & 31;
    int s = g_rowstart[warp];
    int e = g_rowstart[warp + 1];
    float4 acc = make_float4(0.f, 0.f, 0.f, 0.f);
    int j = s;
    for (; j + 1 < e; j += 2) {
        int u0 = g_eidx[j], u1 = g_eidx[j + 1];
        uint2 p0 = *(const uint2*)&g_xh[u0 * HD + lane * 4];
        uint2 p1 = *(const uint2*)&g_xh[u1 * HD + lane * 4];
        float2 a0 = __half22float2(*(const __half2*)&p0.x);
        float2 b0 = __half22float2(*(const __half2*)&p0.y);
        float2 a1 = __half22float2(*(const __half2*)&p1.x);
        float2 b1 = __half22float2(*(const __half2*)&p1.y);
        acc.x += a0.x + a1.x; acc.y += a0.y + a1.y;
        acc.z += b0.x + b1.x; acc.w += b0.y + b1.y;
    }
    if (j < e) {
        int u = g_eidx[j];
        uint2 p = *(const uint2*)&g_xh[u * HD + lane * 4];
        float2 a = __half22float2(*(const __half2*)&p.x);
        float2 b = __half22float2(*(const __half2*)&p.y);
        acc.x += a.x; acc.y += a.y; acc.z += b.x; acc.w += b.y;
    }
    write_hilo(g_ah, g_al, warp, lane, acc);
}

// ---------------- HMMA GEMM: 4 fp16 segments (K=512 effective) -------------
//  (xh + xl) @ Wr_hi  +  (ah + al) @ We_hi ; exact in x/agg, W fp16-rounded.
__global__ void __launch_bounds__(256, 2)
gemm_kernel(const __half* __restrict__ xh, const __half* __restrict__ xl,
            const __half* __restrict__ ah, const __half* __restrict__ al,
            const __half* __restrict__ wr, const __half* __restrict__ we,
            const float* __restrict__ bias, float* __restrict__ yout) {
    extern __shared__ char smem[];
    __shared__ const uint4* Atab[4];
    __shared__ const uint4* Btab[4];
    const int tid = threadIdx.x, lane = tid & 31, wid = tid >> 5;
    const int wm = wid >> 1, wn = wid & 1;
    const int tile = blockIdx.x;

    if (tid == 0) {
        size_t toff = (size_t)tile * 128 * HD;
        Atab[0] = (const uint4*)(xh + toff); Atab[1] = (const uint4*)(ah + toff);
        Atab[2] = (const uint4*)(xl + toff); Atab[3] = (const uint4*)(al + toff);
        Btab[0] = (const uint4*)wr; Btab[1] = (const uint4*)we;
        Btab[2] = (const uint4*)wr; Btab[3] = (const uint4*)we;
    }
    __syncthreads();
    const uint32_t sbase = smem_to_u32(smem);

    auto prefetch = [&](int cc, int st) {
        int seg = cc >> 1, ko4 = (cc & 1) << 3;
        const uint4* As = Atab[seg];
        const uint4* Bs = Btab[seg];
        uint32_t sA = sbase + st * 32768;
        uint32_t sB = sA + 16384;
        #pragma unroll
        for (int i = 0; i < 4; i++) {
            int idx = tid + 256 * i;
            int row = idx >> 3, c4 = idx & 7;
            int sw = (row * 8 + (c4 ^ (row & 7))) * 16;
            CP_ASYNC16(sA + sw, As + row * 16 + ko4 + c4);
            CP_ASYNC16(sB + sw, Bs + row * 16 + ko4 + c4);
        }
    };

    prefetch(0, 0); CP_COMMIT();
    prefetch(1, 1); CP_COMMIT();
    prefetch(2, 2); CP_COMMIT();

    float acc[2][8][4] = {};
    int st = 0;
    #pragma unroll 1
    for (int c = 0; c < 8; c++) {
        CP_WAIT2();
        __syncthreads();
        uint32_t sA = sbase + st * 32768;
        uint32_t sB = sA + 16384;
        #pragma unroll
        for (int kk = 0; kk < 4; kk++) {
            uint32_t a0[4], a1[4];
            {
                int row = wm * 32 + (lane & 15);
                int c4 = kk * 2 + (lane >> 4);
                ldsm_x4(a0, sA + (row * 8 + (c4 ^ (row & 7))) * 16);
                int row1 = row + 16;
                ldsm_x4(a1, sA + (row1 * 8 + (c4 ^ (row1 & 7))) * 16);
            }
            uint32_t b[4][4];
            #pragma unroll
            for (int p = 0; p < 4; p++) {
                int nrow = wn * 64 + p * 16 + ((lane >> 4) << 3) + (lane & 7);
                int c4 = kk * 2 + ((lane >> 3) & 1);
                ldsm_x4(b[p], sB + (nrow * 8 + (c4 ^ (nrow & 7))) * 16);
            }
            #pragma unroll
            for (int nt = 0; nt < 8; nt++) {
                mma16816(acc[0][nt], a0, &b[nt >> 1][(nt & 1) * 2]);
                mma16816(acc[1][nt], a1, &b[nt >> 1][(nt & 1) * 2]);
            }
        }
        __syncthreads();
        if (c + 3 < 8) prefetch(c + 3, st);
        CP_COMMIT();
        st = (st == 2) ? 0 : st + 1;
    }

    int r0 = tile * 128 + wm * 32 + (lane >> 2);
    int cb = wn * 64 + (lane & 3) * 2;
    #pragma unroll
    for (int mt = 0; mt < 2; mt++) {
        #pragma unroll
        for (int nt = 0; nt < 8; nt++) {
            int col = cb + nt * 8;
            int row = r0 + mt * 16;
            float bx = bias[col], by = bias[col + 1];
            float2 v;
            v.x = fmaxf(acc[mt][nt][0] + bx, 0.f);
            v.y = fmaxf(acc[mt][nt][1] + by, 0.f);
            *(float2*)&yout[(size_t)row * HD + col] = v;
            v.x = fmaxf(acc[mt][nt][2] + bx, 0.f);
            v.y = fmaxf(acc[mt][nt][3] + by, 0.f);
            *(float2*)&yout[(size_t)(row + 8) * HD + col] = v;
        }
    }
}

// ---------------- mixup: writes fp16 hi/lo of new x ------------------------
__global__ void mixup_kernel(const float* __restrict__ lam, int which,
                             const float* __restrict__ yin) {
    int warp = (blockIdx.x * blockDim.x + threadIdx.x) >> 5;
    if (warp >= NN) return;
    int lane = threadIdx.x & 31;
    const int* perm = which ? g_p2 : g_p1;
    int p = perm[warp];
    float l = lam[0];
    float4 a = *(const float4*)&yin[(size_t)warp * HD + lane * 4];
    float4 b = *(const float4*)&yin[(size_t)p * HD + lane * 4];
    float4 o;
    o.x = l * a.x + (1.f - l) * b.x;
    o.y = l * a.y + (1.f - l) * b.y;
    o.z = l * a.z + (1.f - l) * b.z;
    o.w = l * a.w + (1.f - l) * b.w;
    write_hilo(g_xh, g_xl, warp, lane, o);
}

// ---------------- pooling (mixup3 no-op under segment-sum) -----------------
__global__ void pool_kernel(const float* __restrict__ yin) {
    int g = blockIdx.x >> 2;
    int c = blockIdx.x & 3;
    int t = threadIdx.x;
    float acc = 0.f;
    int base = g * SEG + c * 100;
    #pragma unroll 4
    for (int r = 0; r < 100; r++)
        acc += yin[(size_t)(base + r) * HD + t];
    atomicAdd(&g_pooled[g * HD + t], acc);
}

// ---------------- head -----------------------------------------------------
__global__ void head_kernel(const float* __restrict__ Wl,
                            const float* __restrict__ bl,
                            float* __restrict__ out) {
    int g = blockIdx.x;
    int lane = threadIdx.x;
    float pv[4];
    #pragma unroll
    for (int q = 0; q < 4; q++) pv[q] = g_pooled[g * HD + lane + q * 32];
    float logits[OUTC];
    #pragma unroll
    for (int o = 0; o < OUTC; o++) {
        float s = 0.f;
        #pragma unroll
        for (int q = 0; q < 4; q++)
            s += pv[q] * Wl[(lane + q * 32) * OUTC + o];
        #pragma unroll
        for (int off = 16; off; off >>= 1)
            s += __shfl_down_sync(0xffffffffu, s, off);
        logits[o] = s;
    }
    if (lane == 0) {
        float m = -1e30f;
        #pragma unroll
        for (int o = 0; o < OUTC; o++) {
            logits[o] += bl[o];
            m = fmaxf(m, logits[o]);
        }
        float se = 0.f;
        #pragma unroll
        for (int o = 0; o < OUTC; o++) se += expf(logits[o] - m);
        float lse = m + logf(se);
        #pragma unroll
        for (int o = 0; o < OUTC; o++) out[g * OUTC + o] = logits[o] - lse;
    }
}

// ---------------- launch ----------------------------------------------------
extern "C" void kernel_launch(void* const* d_in, const int* in_sizes, int n_in,
                              void* d_out, int out_size) {
    const float* x0      = (const float*)d_in[0];
    const void*  eidx    = d_in[1];
    const float* lam     = (const float*)d_in[2];
    const void*  perm1   = d_in[5];
    const void*  perm2   = d_in[6];
    const float* W1_rel  = (const float*)d_in[8];
    const float* b1_rel  = (const float*)d_in[9];
    const float* W1_root = (const float*)d_in[10];
    const float* W2_rel  = (const float*)d_in[11];
    const float* b2_rel  = (const float*)d_in[12];
    const float* W2_root = (const float*)d_in[13];
    const float* W_lin   = (const float*)d_in[14];
    const float* b_lin   = (const float*)d_in[15];
    float* out = (float*)d_out;

    const int GEMM_SMEM = 3 * 32768;
    static int smem_set = 0;
    if (!smem_set) {
        cudaFuncSetAttribute(gemm_kernel,
                             cudaFuncAttributeMaxDynamicSharedMemorySize, GEMM_SMEM);
        smem_set = 1;
    }

    init_kernel<<<(NN + 255) / 256, 256>>>((const unsigned*)eidx);
    convhist_kernel<<<(NE + 255) / 256, 256>>>(eidx, perm1, perm2);
    scan1_kernel<<<(NN + 255) / 256, 256>>>();
    scan2_kernel<<<1, 256>>>();
    scan3_kernel<<<(NN + 255) / 256, 256>>>();
    scatter_kernel<<<(NE + 255) / 256, 256>>>();

    wprep_kernel<<<4, 128>>>(W1_root, W1_rel, W2_root, W2_rel);
    xprep_kernel<<<(NN * 32 + 255) / 256, 256>>>(x0);

    __half *xh, *xl, *ah, *al, *w;
    float *gy;
    cudaGetSymbolAddress((void**)&xh, g_xh);
    cudaGetSymbolAddress((void**)&xl, g_xl);
    cudaGetSymbolAddress((void**)&ah, g_ah);
    cudaGetSymbolAddress((void**)&al, g_al);
    cudaGetSymbolAddress((void**)&w,  g_w);
    cudaGetSymbolAddress((void**)&gy, g_y);
    __half* w0r = w + 0 * HD * HD;
    __half* w0e = w + 1 * HD * HD;
    __half* w1r = w + 2 * HD * HD;
    __half* w1e = w + 3 * HD * HD;

    // Layer 1
    agg_kernel<<<(NN * 32 + 255) / 256, 256>>>();
    gemm_kernel<<<NT, 256, GEMM_SMEM>>>(xh, xl, ah, al, w0r, w0e, b1_rel, gy);
    mixup_kernel<<<(NN * 32 + 255) / 256, 256>>>(lam, 0, gy);

    // Layer 2
    agg_kernel<<<(NN * 32 + 255) / 256, 256>>>();
    gemm_kernel<<<NT, 256, GEMM_SMEM>>>(xh, xl, ah, al, w1r, w1e, b2_rel, gy);
    mixup_kernel<<<(NN * 32 + 255) / 256, 256>>>(lam, 1, gy);

    // Layer 3 (conv2 weights reused; mixup3 invariant under pooling)
    agg_kernel<<<(NN * 32 + 255) / 256, 256>>>();
    gemm_kernel<<<NT, 256, GEMM_SMEM>>>(xh, xl, ah, al, w1r, w1e, b2_rel, gy);

    pool_kernel<<<NG * 4, 128>>>(gy);
    head_kernel<<<NG, 32>>>(W_lin, b_lin, out);
}